// round 12
// baseline (speedup 1.0000x reference)
#include <cuda_runtime.h>

#define EPSF 1e-10f
#define NI 100000
#define NU 100000
#define NR 6
#define BB 512
#define PP 100
#define QQ 40
#define P2 40
#define XS 12  // XT row stride (floats)

typedef unsigned long long ull;

// ---------------- persistent scratch (static device memory) -----------------
__device__ float g_iP[NI * 64];            // item_table @ W1_top
__device__ float g_uPA1[NU * 64];          // user_table @ A1_bot
__device__ float g_rP[NR * 64];            // rate_table @ W1_bot + gv_b1
__device__ float g_Wf[64 * 64];            // W2 @ A1_top
__device__ float g_bf[64];                 // b2 @ A1_top + b1a
__device__ float g_Wg[64 * 64];            // W2 @ agg_W
__device__ float g_bg[64];                 // b2 @ agg_W
__device__ float g_T2[(long)NR * NI * 64]; // T2 = h1@Wf + bf per (rate,item)
__device__ float g_hoI[BB * QQ * 64];
__device__ float g_hiI[BB * 64];
__device__ float g_hiS[BB * 64];

// ------------------------- f32x2 packed helpers ----------------------------
__device__ __forceinline__ ull pk2(float lo, float hi) {
  ull r; asm("mov.b64 %0, {%1,%2};" : "=l"(r) : "f"(lo), "f"(hi)); return r;
}
__device__ __forceinline__ void fma2(ull& d, ull a, ull b) {
  asm("fma.rn.f32x2 %0, %1, %2, %0;" : "+l"(d) : "l"(a), "l"(b));
}
__device__ __forceinline__ void upk(ull v, float& lo, float& hi) {
  asm("mov.b64 {%0,%1}, %2;" : "=f"(lo), "=f"(hi) : "l"(v));
}

// ---------------------------------------------------------------------------
// packed 5-row warp GEMM (XT stride 8): rows 0-3 as two f32x2 pairs, row 4
// scalar. Bitwise identical to the scalar version.
// ---------------------------------------------------------------------------
template <int K>
__device__ __forceinline__ void wgemm2(const float* __restrict__ sXT,
                                       const float* __restrict__ sW, int lane,
                                       ull a0[2], ull a1[2], float& s40, float& s41) {
#pragma unroll 8
  for (int k = 0; k < K; k++) {
    ulonglong2 xu = *reinterpret_cast<const ulonglong2*>(sXT + k * 8); // rows 0..3
    float x5 = sXT[k * 8 + 4];
    float2 wv = *reinterpret_cast<const float2*>(sW + k * 64 + 2 * lane);
    ull w0 = pk2(wv.x, wv.x), w1 = pk2(wv.y, wv.y);
    fma2(a0[0], xu.x, w0); fma2(a1[0], xu.x, w1);
    fma2(a0[1], xu.y, w0); fma2(a1[1], xu.y, w1);
    s40 = fmaf(x5, wv.x, s40); s41 = fmaf(x5, wv.y, s41);
  }
}
__device__ __forceinline__ void unpack5(const ull a0[2], const ull a1[2],
                                        float s40, float s41, float acc[5][2]) {
  upk(a0[0], acc[0][0], acc[1][0]); upk(a0[1], acc[2][0], acc[3][0]);
  upk(a1[0], acc[0][1], acc[1][1]); upk(a1[1], acc[2][1], acc[3][1]);
  acc[4][0] = s40; acc[4][1] = s41;
}
__device__ __forceinline__ void wtrans(float* sT, int lane, const float acc[5][2]) {
#pragma unroll
  for (int j = 0; j < 5; j++) {
    sT[(2 * lane) * 8 + j]     = acc[j][0];
    sT[(2 * lane + 1) * 8 + j] = acc[j][1];
  }
}

// ---------------------------------------------------------------------------
// K0_pre (parallel): grid 33.
// ---------------------------------------------------------------------------
__global__ __launch_bounds__(256) void k0_pre(
    const float* __restrict__ rate_table, const float* __restrict__ gv_W1,
    const float* __restrict__ gv_b1, const float* __restrict__ gv_W2,
    const float* __restrict__ gv_b2, const float* __restrict__ atti_W1,
    const float* __restrict__ atti_b1, const float* __restrict__ agg_W) {
  int b = blockIdx.x, t = threadIdx.x;
  if (b < 16) {
    int idx = b * 256 + t;
    int k = idx >> 6, c = idx & 63;
    float s = 0.f;
#pragma unroll 8
    for (int j = 0; j < 64; j++) s = fmaf(gv_W2[k * 64 + j], atti_W1[j * 64 + c], s);
    g_Wf[idx] = s;
  } else if (b < 32) {
    int idx = (b - 16) * 256 + t;
    int k = idx >> 6, c = idx & 63;
    float s = 0.f;
#pragma unroll 8
    for (int j = 0; j < 64; j++) s = fmaf(gv_W2[k * 64 + j], agg_W[j * 64 + c], s);
    g_Wg[idx] = s;
  } else {
    for (int i = t; i < NR * 64; i += 256) {
      int r = i >> 6, c = i & 63;
      float s = gv_b1[c];
      const float* W1b = gv_W1 + 4096;
#pragma unroll 8
      for (int k = 0; k < 64; k++) s = fmaf(rate_table[r * 64 + k], W1b[k * 64 + c], s);
      g_rP[i] = s;
    }
    if (t < 64) {
      float s = atti_b1[t], sg = 0.f;
#pragma unroll 8
      for (int j = 0; j < 64; j++) {
        s = fmaf(gv_b2[j], atti_W1[j * 64 + t], s);
        sg = fmaf(gv_b2[j], agg_W[j * 64 + t], sg);
      }
      g_bf[t] = s;
      g_bg[t] = sg;
    }
  }
}

// ---------------------------------------------------------------------------
// K0_proj (FFMA2, packed x loads, software-pipelined staging)
// ---------------------------------------------------------------------------
#define SMEM_K0P ((4096 + 4096 + 8 * 64 * XS) * 4)
__global__ __launch_bounds__(256) void k0_proj(
    const float* __restrict__ item_table, const float* __restrict__ user_table,
    const float* __restrict__ gv_W1, const float* __restrict__ atti_W1) {
  extern __shared__ float sm[];
  float* sWa = sm;
  float* sWb = sm + 4096;
  float* sXT = sm + 8192;

  int tid = threadIdx.x, lane = tid & 31, w = tid >> 5;
  for (int i = tid; i < 4096; i += 256) { sWa[i] = gv_W1[i]; sWb[i] = atti_W1[4096 + i]; }
  __syncthreads();
  float* myXT = sXT + w * (64 * XS);

  float pa[10], pb[10];
  // prefetch tile 0
  {
    int rid0 = blockIdx.x * 400 + w * 10;
    bool h2 = (rid0 >= NI);
    const float* src = h2 ? user_table : item_table;
    int base = h2 ? (rid0 - NI) : rid0;
#pragma unroll
    for (int j = 0; j < 10; j++) {
      const float* sp = src + (long)(base + j) * 64;
      pa[j] = sp[lane]; pb[j] = sp[lane + 32];
    }
  }

  for (int it = 0; it < 5; it++) {
    int rid0 = blockIdx.x * 400 + it * 80 + w * 10;
    bool half2 = (rid0 >= NI);
    const float* sW = half2 ? sWb : sWa;
    float* dst = half2 ? g_uPA1 : g_iP;
    int base = half2 ? (rid0 - NI) : rid0;
#pragma unroll
    for (int j = 0; j < 10; j++) {
      myXT[lane * XS + j] = pa[j];
      myXT[(lane + 32) * XS + j] = pb[j];
    }
    __syncwarp();
    // prefetch next tile while GEMM runs
    if (it < 4) {
      int ridn = blockIdx.x * 400 + (it + 1) * 80 + w * 10;
      bool h2n = (ridn >= NI);
      const float* srcn = h2n ? user_table : item_table;
      int basen = h2n ? (ridn - NI) : ridn;
#pragma unroll
      for (int j = 0; j < 10; j++) {
        const float* sp = srcn + (long)(basen + j) * 64;
        pa[j] = sp[lane]; pb[j] = sp[lane + 32];
      }
    }
    ull a0[5], a1[5];
#pragma unroll
    for (int p = 0; p < 5; p++) { a0[p] = 0ull; a1[p] = 0ull; }
#pragma unroll 8
    for (int k = 0; k < 64; k++) {
      ulonglong2 xu0 = *reinterpret_cast<const ulonglong2*>(myXT + k * XS);
      ulonglong2 xu1 = *reinterpret_cast<const ulonglong2*>(myXT + k * XS + 4);
      ull xp4 = *reinterpret_cast<const ull*>(myXT + k * XS + 8);
      float2 wv = *reinterpret_cast<const float2*>(sW + k * 64 + 2 * lane);
      ull w0 = pk2(wv.x, wv.x), w1 = pk2(wv.y, wv.y);
      fma2(a0[0], xu0.x, w0); fma2(a1[0], xu0.x, w1);
      fma2(a0[1], xu0.y, w0); fma2(a1[1], xu0.y, w1);
      fma2(a0[2], xu1.x, w0); fma2(a1[2], xu1.x, w1);
      fma2(a0[3], xu1.y, w0); fma2(a1[3], xu1.y, w1);
      fma2(a0[4], xp4, w0);   fma2(a1[4], xp4, w1);
    }
#pragma unroll
    for (int p = 0; p < 5; p++) {
      float r0c0, r1c0, r0c1, r1c1;
      upk(a0[p], r0c0, r1c0); upk(a1[p], r0c1, r1c1);
      *reinterpret_cast<float2*>(dst + (long)(base + 2 * p) * 64 + 2 * lane) =
          make_float2(r0c0, r0c1);
      *reinterpret_cast<float2*>(dst + (long)(base + 2 * p + 1) * 64 + 2 * lane) =
          make_float2(r1c0, r1c1);
    }
    __syncwarp();
  }
}

// ---------------------------------------------------------------------------
// K0_combo (FFMA2, single GEMM, packed x loads, software-pipelined staging)
// ---------------------------------------------------------------------------
#define SMEM_K0C ((4096 + 8 * 64 * XS + 384 + 64) * 4)
__global__ __launch_bounds__(256) void k0_combo() {
  extern __shared__ float sm[];
  float* sWf = sm;                  // 4096
  float* sXT = sm + 4096;           // 6144
  float* srP = sm + 4096 + 6144;    // 384
  float* sbf = srP + 384;           // 64

  int tid = threadIdx.x, lane = tid & 31, w = tid >> 5;
  for (int i = tid; i < 4096; i += 256) sWf[i] = g_Wf[i];
  for (int i = tid; i < 384; i += 256) srP[i] = g_rP[i];
  if (tid < 64) sbf[tid] = g_bf[tid];
  __syncthreads();
  float* myXT = sXT + w * (64 * XS);

  float2 bb2 = *reinterpret_cast<const float2*>(sbf + 2 * lane);
  ull b20 = pk2(bb2.x, bb2.x), b21 = pk2(bb2.y, bb2.y);

  float pa[10], pb[10];
  // prefetch tile 0
  {
    int rid0 = blockIdx.x * 320 + w * 10;
    int r0 = rid0 / NI;
    int i0 = rid0 - r0 * NI;
#pragma unroll
    for (int j = 0; j < 10; j++) {
      const float* ip = g_iP + (long)(i0 + j) * 64;
      pa[j] = ip[lane]; pb[j] = ip[lane + 32];
    }
  }

  for (int it = 0; it < 4; it++) {
    int rid0 = blockIdx.x * 320 + it * 80 + w * 10;
    int r = rid0 / NI;
    const float* rp = srP + r * 64;
    float rp0 = rp[lane], rp1 = rp[lane + 32];
#pragma unroll
    for (int j = 0; j < 10; j++) {
      myXT[lane * XS + j] = fmaxf(pa[j] + rp0, 0.f);
      myXT[(lane + 32) * XS + j] = fmaxf(pb[j] + rp1, 0.f);
    }
    __syncwarp();
    // prefetch next tile while GEMM runs
    if (it < 3) {
      int ridn = blockIdx.x * 320 + (it + 1) * 80 + w * 10;
      int rn = ridn / NI;
      int in0 = ridn - rn * NI;
#pragma unroll
      for (int j = 0; j < 10; j++) {
        const float* ip = g_iP + (long)(in0 + j) * 64;
        pa[j] = ip[lane]; pb[j] = ip[lane + 32];
      }
    }
    ull a20[5], a21[5];
#pragma unroll
    for (int p = 0; p < 5; p++) { a20[p] = b20; a21[p] = b21; }
#pragma unroll 8
    for (int k = 0; k < 64; k++) {
      ulonglong2 xu0 = *reinterpret_cast<const ulonglong2*>(myXT + k * XS);
      ulonglong2 xu1 = *reinterpret_cast<const ulonglong2*>(myXT + k * XS + 4);
      ull xp4 = *reinterpret_cast<const ull*>(myXT + k * XS + 8);
      float2 w2v = *reinterpret_cast<const float2*>(sWf + k * 64 + 2 * lane);
      ull w20 = pk2(w2v.x, w2v.x), w21 = pk2(w2v.y, w2v.y);
      fma2(a20[0], xu0.x, w20); fma2(a21[0], xu0.x, w21);
      fma2(a20[1], xu0.y, w20); fma2(a21[1], xu0.y, w21);
      fma2(a20[2], xu1.x, w20); fma2(a21[2], xu1.x, w21);
      fma2(a20[3], xu1.y, w20); fma2(a21[3], xu1.y, w21);
      fma2(a20[4], xp4, w20);   fma2(a21[4], xp4, w21);
    }
#pragma unroll
    for (int p = 0; p < 5; p++) {
      float r0c0, r1c0, r0c1, r1c1;
      long o0 = (long)(rid0 + 2 * p) * 64 + 2 * lane;
      long o1 = (long)(rid0 + 2 * p + 1) * 64 + 2 * lane;
      upk(a20[p], r0c0, r1c0); upk(a21[p], r0c1, r1c1);
      *reinterpret_cast<float2*>(g_T2 + o0) = make_float2(r0c0, r0c1);
      *reinterpret_cast<float2*>(g_T2 + o1) = make_float2(r1c0, r1c1);
    }
    __syncwarp();
  }
}

// ---------------------------------------------------------------------------
// K2s1: merged attention kernel, fused oct-slice, 5 CTAs/SM.
//  blocks [0,64): item branch; blocks [64, 64+2560): social branch.
// ---------------------------------------------------------------------------
__global__ __launch_bounds__(256, 5) void k2s1_attn(
    const int* __restrict__ uids,
    const int* __restrict__ u_user, const int* __restrict__ u_user_item,
    const int* __restrict__ u_item,
    const float* __restrict__ agg_b,
    const float* __restrict__ atti_W2, const float* __restrict__ atti_b2) {
  __shared__ float sWg[4096];
  __shared__ float srP[384];
  __shared__ float sbAgg[64];
  __shared__ float sbg[64];
  __shared__ float sA2[64];
  __shared__ float sPC[8][64];
  __shared__ float sPart[8][4][64];   // [warp][oct][col]
  __shared__ float sZ[8][64];

  int bx = blockIdx.x, tid = threadIdx.x, lane = tid & 31, w = tid >> 5;
  for (int i = tid; i < 4096; i += 256) sWg[i] = g_Wg[i];
  for (int i = tid; i < 384; i += 256) srP[i] = g_rP[i];
  if (tid < 64) { sbAgg[tid] = agg_b[tid]; sbg[tid] = g_bg[tid]; sA2[tid] = atti_W2[tid]; }
  __syncthreads();
  float cb = atti_b2[0];

  bool item = (bx < 64);
  int unit = item ? (bx * 8 + w) : ((bx - 64) * 8 + w);  // b or gid
  int P = item ? PP : P2;
  int u = item ? uids[unit] : u_user[unit];
  const int2* ips = reinterpret_cast<const int2*>(
      item ? (u_item + (long)unit * (PP * 2)) : (u_user_item + (long)unit * (P2 * 2)));
  float* outp = item ? (g_hiI + (long)unit * 64) : (g_hoI + (long)unit * 64);

  // stage pc for this unit into smem (per-warp row)
  sPC[w][lane] = g_uPA1[(long)u * 64 + lane];
  sPC[w][lane + 32] = g_uPA1[(long)u * 64 + 32 + lane];
  __syncwarp();

  int li = lane & 7, oct = lane >> 3;  // 8 lanes per row, 4 rows per iter
  float4 a2r0 = *reinterpret_cast<const float4*>(sA2 + li * 8);
  float4 a2r1 = *reinterpret_cast<const float4*>(sA2 + li * 8 + 4);

  float4 acca = make_float4(0.f, 0.f, 0.f, 0.f);
  float4 accb = make_float4(0.f, 0.f, 0.f, 0.f);
  float den = 0.f;
  int niter = P >> 2;  // 40->10, 100->25 (exact)
  for (int it = 0; it < niter; it++) {
    int r = it * 4 + oct;
    int2 idx = ips[r];
    float m = (idx.x > 0) ? 1.f : 0.f;
    long rid = (long)(idx.y * NI + idx.x);
    const float4* t2p = reinterpret_cast<const float4*>(g_T2 + rid * 64 + li * 8);
    float4 t2a = t2p[0], t2b = t2p[1];
    const float4* ipp = reinterpret_cast<const float4*>(g_iP + (long)idx.x * 64 + li * 8);
    float4 ipa = ipp[0], ipb = ipp[1];
    const float4* rpp = reinterpret_cast<const float4*>(srP + idx.y * 64 + li * 8);
    float4 rpa = rpp[0], rpb = rpp[1];
    const float4* pcp = reinterpret_cast<const float4*>(&sPC[w][li * 8]);
    float4 pcr0 = pcp[0], pcr1 = pcp[1];
    float s;
    s = fmaxf(fmaf(m, pcr0.x, t2a.x), 0.f) * a2r0.x;
    s = fmaf(fmaxf(fmaf(m, pcr0.y, t2a.y), 0.f), a2r0.y, s);
    s = fmaf(fmaxf(fmaf(m, pcr0.z, t2a.z), 0.f), a2r0.z, s);
    s = fmaf(fmaxf(fmaf(m, pcr0.w, t2a.w), 0.f), a2r0.w, s);
    s = fmaf(fmaxf(fmaf(m, pcr1.x, t2b.x), 0.f), a2r1.x, s);
    s = fmaf(fmaxf(fmaf(m, pcr1.y, t2b.y), 0.f), a2r1.y, s);
    s = fmaf(fmaxf(fmaf(m, pcr1.z, t2b.z), 0.f), a2r1.z, s);
    s = fmaf(fmaxf(fmaf(m, pcr1.w, t2b.w), 0.f), a2r1.w, s);
    s += __shfl_xor_sync(0xffffffffu, s, 1);
    s += __shfl_xor_sync(0xffffffffu, s, 2);
    s += __shfl_xor_sync(0xffffffffu, s, 4);
    float al = __expf(s + cb) * m;
    den += al;
    acca.x = fmaf(al, fmaxf(ipa.x + rpa.x, 0.f), acca.x);
    acca.y = fmaf(al, fmaxf(ipa.y + rpa.y, 0.f), acca.y);
    acca.z = fmaf(al, fmaxf(ipa.z + rpa.z, 0.f), acca.z);
    acca.w = fmaf(al, fmaxf(ipa.w + rpa.w, 0.f), acca.w);
    accb.x = fmaf(al, fmaxf(ipb.x + rpb.x, 0.f), accb.x);
    accb.y = fmaf(al, fmaxf(ipb.y + rpb.y, 0.f), accb.y);
    accb.z = fmaf(al, fmaxf(ipb.z + rpb.z, 0.f), accb.z);
    accb.w = fmaf(al, fmaxf(ipb.w + rpb.w, 0.f), accb.w);
  }
#pragma unroll
  for (int o = 16; o; o >>= 1) den += __shfl_xor_sync(0xffffffffu, den, o);
  den *= 0.125f;  // each row's alpha counted 8x (once per oct lane)
  float dinv = 1.f / (den + EPSF);
  float sig = den * dinv;

  // combine oct partials: sPart[w][oct][col]
  *reinterpret_cast<float4*>(&sPart[w][oct][li * 8]) = acca;
  *reinterpret_cast<float4*>(&sPart[w][oct][li * 8 + 4]) = accb;
  __syncwarp();
  int c0 = 2 * lane;
  float zx = sPart[w][0][c0] + sPart[w][1][c0] + sPart[w][2][c0] + sPart[w][3][c0];
  float zy = sPart[w][0][c0 + 1] + sPart[w][1][c0 + 1] + sPart[w][2][c0 + 1] + sPart[w][3][c0 + 1];
  sZ[w][c0] = zx * dinv;
  sZ[w][c0 + 1] = zy * dinv;
  __syncwarp();

  // epilogue GEMV: out = relu(z@Wg + sig*bg + agg_b)
  float ox = fmaf(sig, sbg[c0], sbAgg[c0]);
  float oy = fmaf(sig, sbg[c0 + 1], sbAgg[c0 + 1]);
#pragma unroll 8
  for (int k = 0; k < 64; k++) {
    float zk = sZ[w][k];
    float2 wk = *reinterpret_cast<const float2*>(sWg + k * 64 + c0);
    ox = fmaf(zk, wk.x, ox); oy = fmaf(zk, wk.y, oy);
  }
  *reinterpret_cast<float2*>(outp + c0) =
      make_float2(fmaxf(ox, 0.f), fmaxf(oy, 0.f));
}

// ---------------------------------------------------------------------------
// K2b: beta attention over q + h_iS. FFMA2 GEMM, 2 batch elements per CTA.
// grid 256.
// ---------------------------------------------------------------------------
#define SMEM_K2B (20784 * 4)
__global__ __launch_bounds__(256) void k2b_user(
    const int* __restrict__ u_user, const float* __restrict__ user_table,
    const float* __restrict__ attu_W1, const float* __restrict__ attu_b1,
    const float* __restrict__ attu_W2, const float* __restrict__ attu_b2,
    const float* __restrict__ aggn_W, const float* __restrict__ aggn_b) {
  extern __shared__ float sm[];
  float* sU1 = sm;             float* sAggn = sm + 8192;
  float* sw2u = sm + 12288;    float* sb1u = sm + 12352;
  float* sbAggn = sm + 12416;  float* sZ = sm + 12480;
  float* sBeta = sm + 12544;   float* sRed = sm + 12584;
  float* sXT = sm + 12592;

  int tid = threadIdx.x, lane = tid & 31, w = tid >> 5;
  for (int i = tid; i < 8192; i += 256) sU1[i] = attu_W1[i];
  for (int i = tid; i < 4096; i += 256) sAggn[i] = aggn_W[i];
  if (tid < 64) { sw2u[tid] = attu_W2[tid]; sb1u[tid] = attu_b1[tid]; sbAggn[tid] = aggn_b[tid]; }
  __syncthreads();
  float cb2u = attu_b2[0];
  float* myXT = sXT + w * 1024;
  int rowbase = w * 5;

  for (int bi = 0; bi < 2; bi++) {
    int b = blockIdx.x * 2 + bi;
    __syncthreads();
    float msk[5];
#pragma unroll
    for (int j = 0; j < 5; j++) {
      int row = rowbase + j;
      int uq = u_user[b * 40 + row];
      msk[j] = (uq > 0) ? 1.f : 0.f;
      const float* hp = g_hoI + (long)(b * 40 + row) * 64;
      const float* up = user_table + (long)uq * 64;
      myXT[lane * 8 + j] = hp[lane]; myXT[(lane + 32) * 8 + j] = hp[lane + 32];
      myXT[(lane + 64) * 8 + j] = up[lane]; myXT[(lane + 96) * 8 + j] = up[lane + 32];
    }
    __syncwarp();
    float bc0 = sb1u[2 * lane], bc1 = sb1u[2 * lane + 1];
    ull a0[2], a1[2]; float s40 = bc0, s41 = bc1;
    a0[0] = a0[1] = pk2(bc0, bc0); a1[0] = a1[1] = pk2(bc1, bc1);
    wgemm2<128>(myXT, sU1, lane, a0, a1, s40, s41);
    float acc[5][2];
    unpack5(a0, a1, s40, s41, acc);
    float w0 = sw2u[2 * lane], w1 = sw2u[2 * lane + 1];
#pragma unroll
    for (int j = 0; j < 5; j++) {
      float p = fmaf(fmaxf(acc[j][0], 0.f), w0, fmaxf(acc[j][1], 0.f) * w1);
#pragma unroll
      for (int o = 16; o; o >>= 1) p += __shfl_xor_sync(0xffffffffu, p, o);
      if (lane == 0) sBeta[rowbase + j] = expf(p + cb2u) * msk[j];
    }
    __syncthreads();
    if (tid < 32) {
      float s = 0.f;
      for (int r = lane; r < 40; r += 32) s += sBeta[r];
#pragma unroll
      for (int o = 16; o; o >>= 1) s += __shfl_xor_sync(0xffffffffu, s, o);
      if (lane == 0) sRed[0] = s;
    }
    __syncthreads();
    float dinv = 1.f / (sRed[0] + EPSF);
    if (tid < 64) {
      float s = 0.f;
      for (int r = 0; r < 40; r++) s = fmaf(sBeta[r], g_hoI[(long)(b * 40 + r) * 64 + tid], s);
      sZ[tid] = s * dinv;
    }
    __syncthreads();
    if (tid < 64) {
      float s = sbAggn[tid];
      for (int k = 0; k < 64; k++) s = fmaf(sZ[k], sAggn[k * 64 + tid], s);
      g_hiS[b * 64 + tid] = fmaxf(s, 0.f);
    }
  }
}

// ---------------------------------------------------------------------------
// K3: final 3-layer combine MLP (FFMA2).
// ---------------------------------------------------------------------------
#define SMEM_K3 (24768 * 4)
__global__ __launch_bounds__(256) void k3_final(
    const float* __restrict__ cm_W1, const float* __restrict__ cm_b1,
    const float* __restrict__ cm_W2, const float* __restrict__ cm_b2,
    const float* __restrict__ cm_W3, const float* __restrict__ cm_b3,
    float* __restrict__ out) {
  extern __shared__ float sm[];
  float* sC1 = sm;          float* sC2 = sm + 8192;   float* sC3 = sm + 12288;
  float* sb1 = sm + 16384;  float* sb2 = sm + 16448;  float* sb3 = sm + 16512;
  float* sXT = sm + 16576;

  int tid = threadIdx.x, lane = tid & 31, w = tid >> 5;
  for (int i = tid; i < 8192; i += 256) sC1[i] = cm_W1[i];
  for (int i = tid; i < 4096; i += 256) { sC2[i] = cm_W2[i]; sC3[i] = cm_W3[i]; }
  if (tid < 64) { sb1[tid] = cm_b1[tid]; sb2[tid] = cm_b2[tid]; sb3[tid] = cm_b3[tid]; }
  __syncthreads();
  float* myXT = sXT + w * 1024;
  int rowbase = blockIdx.x * 40 + w * 5;
#pragma unroll
  for (int j = 0; j < 5; j++) {
    int row = rowbase + j;
    float x0 = 0, x1 = 0, x2 = 0, x3 = 0;
    if (row < BB) {
      x0 = g_hiI[row * 64 + lane]; x1 = g_hiI[row * 64 + 32 + lane];
      x2 = g_hiS[row * 64 + lane]; x3 = g_hiS[row * 64 + 32 + lane];
    }
    myXT[lane * 8 + j] = x0; myXT[(lane + 32) * 8 + j] = x1;
    myXT[(lane + 64) * 8 + j] = x2; myXT[(lane + 96) * 8 + j] = x3;
  }
  __syncwarp();
  float acc[5][2];
  {
    float bc0 = sb1[2 * lane], bc1 = sb1[2 * lane + 1];
    ull a0[2], a1[2]; float s40 = bc0, s41 = bc1;
    a0[0] = a0[1] = pk2(bc0, bc0); a1[0] = a1[1] = pk2(bc1, bc1);
    wgemm2<128>(myXT, sC1, lane, a0, a1, s40, s41);
    unpack5(a0, a1, s40, s41, acc);
  }
#pragma unroll
  for (int j = 0; j < 5; j++) { acc[j][0] = fmaxf(acc[j][0], 0.f); acc[j][1] = fmaxf(acc[j][1], 0.f); }
  __syncwarp(); wtrans(myXT, lane, acc); __syncwarp();
  {
    float bc0 = sb2[2 * lane], bc1 = sb2[2 * lane + 1];
    ull a0[2], a1[2]; float s40 = bc0, s41 = bc1;
    a0[0] = a0[1] = pk2(bc0, bc0); a1[0] = a1[1] = pk2(bc1, bc1);
    wgemm2<64>(myXT, sC2, lane, a0, a1, s40, s41);
    unpack5(a0, a1, s40, s41, acc);
  }
#pragma unroll
  for (int j = 0; j < 5; j++) { acc[j][0] = fmaxf(acc[j][0], 0.f); acc[j][1] = fmaxf(acc[j][1], 0.f); }
  __syncwarp(); wtrans(myXT, lane, acc); __syncwarp();
  {
    float bc0 = sb3[2 * lane], bc1 = sb3[2 * lane + 1];
    ull a0[2], a1[2]; float s40 = bc0, s41 = bc1;
    a0[0] = a0[1] = pk2(bc0, bc0); a1[0] = a1[1] = pk2(bc1, bc1);
    wgemm2<64>(myXT, sC3, lane, a0, a1, s40, s41);
    unpack5(a0, a1, s40, s41, acc);
  }
#pragma unroll
  for (int j = 0; j < 5; j++) {
    int row = rowbase + j;
    if (row < BB) {
      out[row * 64 + 2 * lane]     = fmaxf(acc[j][0], 0.f);
      out[row * 64 + 2 * lane + 1] = fmaxf(acc[j][1], 0.f);
    }
  }
}

// ---------------------------------------------------------------------------
extern "C" void kernel_launch(void* const* d_in, const int* in_sizes, int n_in,
                              void* d_out, int out_size) {
  const int* uids        = (const int*)d_in[0];
  const int* u_item      = (const int*)d_in[1];
  const int* u_user      = (const int*)d_in[2];
  const int* u_user_item = (const int*)d_in[3];
  const float* user_table = (const float*)d_in[4];
  const float* item_table = (const float*)d_in[5];
  const float* rate_table = (const float*)d_in[6];
  const float* gv_W1 = (const float*)d_in[7];   const float* gv_b1 = (const float*)d_in[8];
  const float* gv_W2 = (const float*)d_in[9];   const float* gv_b2 = (const float*)d_in[10];
  const float* atti_W1 = (const float*)d_in[11]; const float* atti_b1 = (const float*)d_in[12];
  const float* atti_W2 = (const float*)d_in[13]; const float* atti_b2 = (const float*)d_in[14];
  const float* agg_W = (const float*)d_in[15];   const float* agg_b = (const float*)d_in[16];
  const float* attu_W1 = (const float*)d_in[17]; const float* attu_b1 = (const float*)d_in[18];
  const float* attu_W2 = (const float*)d_in[19]; const float* attu_b2 = (const float*)d_in[20];
  const float* aggn_W = (const float*)d_in[21];  const float* aggn_b = (const float*)d_in[22];
  const float* cm_W1 = (const float*)d_in[23];   const float* cm_b1 = (const float*)d_in[24];
  const float* cm_W2 = (const float*)d_in[25];   const float* cm_b2 = (const float*)d_in[26];
  const float* cm_W3 = (const float*)d_in[27];   const float* cm_b3 = (const float*)d_in[28];
  float* out = (float*)d_out;

  cudaFuncSetAttribute(k0_proj,  cudaFuncAttributeMaxDynamicSharedMemorySize, SMEM_K0P);
  cudaFuncSetAttribute(k0_combo, cudaFuncAttributeMaxDynamicSharedMemorySize, SMEM_K0C);
  cudaFuncSetAttribute(k2b_user, cudaFuncAttributeMaxDynamicSharedMemorySize, SMEM_K2B);
  cudaFuncSetAttribute(k3_final, cudaFuncAttributeMaxDynamicSharedMemorySize, SMEM_K3);

  k0_pre<<<33, 256>>>(rate_table, gv_W1, gv_b1, gv_W2, gv_b2, atti_W1, atti_b1, agg_W);
  k0_proj<<<500, 256, SMEM_K0P>>>(item_table, user_table, gv_W1, atti_W1);
  k0_combo<<<1875, 256, SMEM_K0C>>>();
  k2s1_attn<<<64 + 2560, 256>>>(uids, u_user, u_user_item, u_item,
                                agg_b, atti_W2, atti_b2);
  k2b_user<<<256, 256, SMEM_K2B>>>(u_user, user_table, attu_W1, attu_b1, attu_W2,
                                   attu_b2, aggn_W, aggn_b);
  k3_final<<<13, 256, SMEM_K3>>>(cm_W1, cm_b1, cm_W2, cm_b2, cm_W3, cm_b3, out);
}

// round 13
// speedup vs baseline: 1.0524x; 1.0524x over previous
#include <cuda_runtime.h>
#include <cuda_fp16.h>

#define EPSF 1e-10f
#define NI 100000
#define NU 100000
#define NR 6
#define BB 512
#define PP 100
#define QQ 40
#define P2 40
#define XS 12  // XT row stride (floats)

typedef unsigned long long ull;

// ---------------- persistent scratch (static device memory) -----------------
__device__ float g_iP[NI * 64];             // item_table @ W1_top
__device__ float g_uPA1[NU * 64];           // user_table @ A1_bot
__device__ float g_rP[NR * 64];             // rate_table @ W1_bot + gv_b1
__device__ float g_Wf[64 * 64];             // W2 @ A1_top
__device__ float g_bf[64];                  // b2 @ A1_top + b1a
__device__ float g_Wg[64 * 64];             // W2 @ agg_W
__device__ float g_bg[64];                  // b2 @ agg_W
__device__ __half g_T2h[(long)NR * NI * 64]; // T2 (fp16) per (rate,item)
__device__ float g_hoI[BB * QQ * 64];
__device__ float g_hiI[BB * 64];
__device__ float g_hiS[BB * 64];

// ------------------------- f32x2 packed helpers ----------------------------
__device__ __forceinline__ ull pk2(float lo, float hi) {
  ull r; asm("mov.b64 %0, {%1,%2};" : "=l"(r) : "f"(lo), "f"(hi)); return r;
}
__device__ __forceinline__ void fma2(ull& d, ull a, ull b) {
  asm("fma.rn.f32x2 %0, %1, %2, %0;" : "+l"(d) : "l"(a), "l"(b));
}
__device__ __forceinline__ void upk(ull v, float& lo, float& hi) {
  asm("mov.b64 {%0,%1}, %2;" : "=f"(lo), "=f"(hi) : "l"(v));
}

// ---------------------------------------------------------------------------
// packed 5-row warp GEMM (XT stride 8): rows 0-3 as two f32x2 pairs, row 4
// scalar. Bitwise identical to the scalar version.
// ---------------------------------------------------------------------------
template <int K>
__device__ __forceinline__ void wgemm2(const float* __restrict__ sXT,
                                       const float* __restrict__ sW, int lane,
                                       ull a0[2], ull a1[2], float& s40, float& s41) {
#pragma unroll 8
  for (int k = 0; k < K; k++) {
    ulonglong2 xu = *reinterpret_cast<const ulonglong2*>(sXT + k * 8); // rows 0..3
    float x5 = sXT[k * 8 + 4];
    float2 wv = *reinterpret_cast<const float2*>(sW + k * 64 + 2 * lane);
    ull w0 = pk2(wv.x, wv.x), w1 = pk2(wv.y, wv.y);
    fma2(a0[0], xu.x, w0); fma2(a1[0], xu.x, w1);
    fma2(a0[1], xu.y, w0); fma2(a1[1], xu.y, w1);
    s40 = fmaf(x5, wv.x, s40); s41 = fmaf(x5, wv.y, s41);
  }
}
__device__ __forceinline__ void unpack5(const ull a0[2], const ull a1[2],
                                        float s40, float s41, float acc[5][2]) {
  upk(a0[0], acc[0][0], acc[1][0]); upk(a0[1], acc[2][0], acc[3][0]);
  upk(a1[0], acc[0][1], acc[1][1]); upk(a1[1], acc[2][1], acc[3][1]);
  acc[4][0] = s40; acc[4][1] = s41;
}
__device__ __forceinline__ void wtrans(float* sT, int lane, const float acc[5][2]) {
#pragma unroll
  for (int j = 0; j < 5; j++) {
    sT[(2 * lane) * 8 + j]     = acc[j][0];
    sT[(2 * lane + 1) * 8 + j] = acc[j][1];
  }
}

// ---------------------------------------------------------------------------
// K0_pre (parallel): grid 33.
// ---------------------------------------------------------------------------
__global__ __launch_bounds__(256) void k0_pre(
    const float* __restrict__ rate_table, const float* __restrict__ gv_W1,
    const float* __restrict__ gv_b1, const float* __restrict__ gv_W2,
    const float* __restrict__ gv_b2, const float* __restrict__ atti_W1,
    const float* __restrict__ atti_b1, const float* __restrict__ agg_W) {
  int b = blockIdx.x, t = threadIdx.x;
  if (b < 16) {
    int idx = b * 256 + t;
    int k = idx >> 6, c = idx & 63;
    float s = 0.f;
#pragma unroll 8
    for (int j = 0; j < 64; j++) s = fmaf(gv_W2[k * 64 + j], atti_W1[j * 64 + c], s);
    g_Wf[idx] = s;
  } else if (b < 32) {
    int idx = (b - 16) * 256 + t;
    int k = idx >> 6, c = idx & 63;
    float s = 0.f;
#pragma unroll 8
    for (int j = 0; j < 64; j++) s = fmaf(gv_W2[k * 64 + j], agg_W[j * 64 + c], s);
    g_Wg[idx] = s;
  } else {
    for (int i = t; i < NR * 64; i += 256) {
      int r = i >> 6, c = i & 63;
      float s = gv_b1[c];
      const float* W1b = gv_W1 + 4096;
#pragma unroll 8
      for (int k = 0; k < 64; k++) s = fmaf(rate_table[r * 64 + k], W1b[k * 64 + c], s);
      g_rP[i] = s;
    }
    if (t < 64) {
      float s = atti_b1[t], sg = 0.f;
#pragma unroll 8
      for (int j = 0; j < 64; j++) {
        s = fmaf(gv_b2[j], atti_W1[j * 64 + t], s);
        sg = fmaf(gv_b2[j], agg_W[j * 64 + t], sg);
      }
      g_bf[t] = s;
      g_bg[t] = sg;
    }
  }
}

// ---------------------------------------------------------------------------
// K0_proj (FFMA2, packed x loads)
// ---------------------------------------------------------------------------
#define SMEM_K0P ((4096 + 4096 + 8 * 64 * XS) * 4)
__global__ __launch_bounds__(256) void k0_proj(
    const float* __restrict__ item_table, const float* __restrict__ user_table,
    const float* __restrict__ gv_W1, const float* __restrict__ atti_W1) {
  extern __shared__ float sm[];
  float* sWa = sm;
  float* sWb = sm + 4096;
  float* sXT = sm + 8192;

  int tid = threadIdx.x, lane = tid & 31, w = tid >> 5;
  for (int i = tid; i < 4096; i += 256) { sWa[i] = gv_W1[i]; sWb[i] = atti_W1[4096 + i]; }
  __syncthreads();
  float* myXT = sXT + w * (64 * XS);

  for (int it = 0; it < 5; it++) {
    int rid0 = blockIdx.x * 400 + it * 80 + w * 10;
    bool half2b = (rid0 >= NI);
    const float* src = half2b ? user_table : item_table;
    const float* sW = half2b ? sWb : sWa;
    float* dst = half2b ? g_uPA1 : g_iP;
    int base = half2b ? (rid0 - NI) : rid0;
#pragma unroll
    for (int j = 0; j < 10; j++) {
      const float* sp = src + (long)(base + j) * 64;
      myXT[lane * XS + j] = sp[lane];
      myXT[(lane + 32) * XS + j] = sp[lane + 32];
    }
    __syncwarp();
    ull a0[5], a1[5];
#pragma unroll
    for (int p = 0; p < 5; p++) { a0[p] = 0ull; a1[p] = 0ull; }
#pragma unroll 8
    for (int k = 0; k < 64; k++) {
      ulonglong2 xu0 = *reinterpret_cast<const ulonglong2*>(myXT + k * XS);
      ulonglong2 xu1 = *reinterpret_cast<const ulonglong2*>(myXT + k * XS + 4);
      ull xp4 = *reinterpret_cast<const ull*>(myXT + k * XS + 8);
      float2 wv = *reinterpret_cast<const float2*>(sW + k * 64 + 2 * lane);
      ull w0 = pk2(wv.x, wv.x), w1 = pk2(wv.y, wv.y);
      fma2(a0[0], xu0.x, w0); fma2(a1[0], xu0.x, w1);
      fma2(a0[1], xu0.y, w0); fma2(a1[1], xu0.y, w1);
      fma2(a0[2], xu1.x, w0); fma2(a1[2], xu1.x, w1);
      fma2(a0[3], xu1.y, w0); fma2(a1[3], xu1.y, w1);
      fma2(a0[4], xp4, w0);   fma2(a1[4], xp4, w1);
    }
#pragma unroll
    for (int p = 0; p < 5; p++) {
      float r0c0, r1c0, r0c1, r1c1;
      upk(a0[p], r0c0, r1c0); upk(a1[p], r0c1, r1c1);
      *reinterpret_cast<float2*>(dst + (long)(base + 2 * p) * 64 + 2 * lane) =
          make_float2(r0c0, r0c1);
      *reinterpret_cast<float2*>(dst + (long)(base + 2 * p + 1) * 64 + 2 * lane) =
          make_float2(r1c0, r1c1);
    }
    __syncwarp();
  }
}

// ---------------------------------------------------------------------------
// K0_combo (FFMA2, single GEMM, fp16 T2 output)
// ---------------------------------------------------------------------------
#define SMEM_K0C ((4096 + 8 * 64 * XS + 384 + 64) * 4)
__global__ __launch_bounds__(256) void k0_combo() {
  extern __shared__ float sm[];
  float* sWf = sm;                  // 4096
  float* sXT = sm + 4096;           // 6144
  float* srP = sm + 4096 + 6144;    // 384
  float* sbf = srP + 384;           // 64

  int tid = threadIdx.x, lane = tid & 31, w = tid >> 5;
  for (int i = tid; i < 4096; i += 256) sWf[i] = g_Wf[i];
  for (int i = tid; i < 384; i += 256) srP[i] = g_rP[i];
  if (tid < 64) sbf[tid] = g_bf[tid];
  __syncthreads();
  float* myXT = sXT + w * (64 * XS);

  float2 bb2 = *reinterpret_cast<const float2*>(sbf + 2 * lane);
  ull b20 = pk2(bb2.x, bb2.x), b21 = pk2(bb2.y, bb2.y);

  for (int it = 0; it < 4; it++) {
    int rid0 = blockIdx.x * 320 + it * 80 + w * 10;
    int r = rid0 / NI;
    int i0 = rid0 - r * NI;
    const float* rp = srP + r * 64;
    float rp0 = rp[lane], rp1 = rp[lane + 32];
#pragma unroll
    for (int j = 0; j < 10; j++) {
      const float* ip = g_iP + (long)(i0 + j) * 64;
      myXT[lane * XS + j] = fmaxf(ip[lane] + rp0, 0.f);
      myXT[(lane + 32) * XS + j] = fmaxf(ip[lane + 32] + rp1, 0.f);
    }
    __syncwarp();
    ull a20[5], a21[5];
#pragma unroll
    for (int p = 0; p < 5; p++) { a20[p] = b20; a21[p] = b21; }
#pragma unroll 8
    for (int k = 0; k < 64; k++) {
      ulonglong2 xu0 = *reinterpret_cast<const ulonglong2*>(myXT + k * XS);
      ulonglong2 xu1 = *reinterpret_cast<const ulonglong2*>(myXT + k * XS + 4);
      ull xp4 = *reinterpret_cast<const ull*>(myXT + k * XS + 8);
      float2 w2v = *reinterpret_cast<const float2*>(sWf + k * 64 + 2 * lane);
      ull w20 = pk2(w2v.x, w2v.x), w21 = pk2(w2v.y, w2v.y);
      fma2(a20[0], xu0.x, w20); fma2(a21[0], xu0.x, w21);
      fma2(a20[1], xu0.y, w20); fma2(a21[1], xu0.y, w21);
      fma2(a20[2], xu1.x, w20); fma2(a21[2], xu1.x, w21);
      fma2(a20[3], xu1.y, w20); fma2(a21[3], xu1.y, w21);
      fma2(a20[4], xp4, w20);   fma2(a21[4], xp4, w21);
    }
#pragma unroll
    for (int p = 0; p < 5; p++) {
      float r0c0, r1c0, r0c1, r1c1;
      upk(a20[p], r0c0, r1c0); upk(a21[p], r0c1, r1c1);
      long o0 = (long)(rid0 + 2 * p) * 64 + 2 * lane;
      long o1 = (long)(rid0 + 2 * p + 1) * 64 + 2 * lane;
      *reinterpret_cast<__half2*>(g_T2h + o0) = __floats2half2_rn(r0c0, r0c1);
      *reinterpret_cast<__half2*>(g_T2h + o1) = __floats2half2_rn(r1c0, r1c1);
    }
    __syncwarp();
  }
}

// ---------------------------------------------------------------------------
// K2s1: merged attention kernel, fused oct-slice, fp16 T2 gather (one LDG.128
// per lane per row). blocks [0,64): item; [64, 64+2560): social.
// ---------------------------------------------------------------------------
__global__ __launch_bounds__(256, 5) void k2s1_attn(
    const int* __restrict__ uids,
    const int* __restrict__ u_user, const int* __restrict__ u_user_item,
    const int* __restrict__ u_item,
    const float* __restrict__ agg_b,
    const float* __restrict__ atti_W2, const float* __restrict__ atti_b2) {
  __shared__ float sWg[4096];
  __shared__ float srP[384];
  __shared__ float sbAgg[64];
  __shared__ float sbg[64];
  __shared__ float sA2[64];
  __shared__ float sPC[8][64];
  __shared__ float sPart[8][4][64];   // [warp][oct][col]
  __shared__ float sZ[8][64];

  int bx = blockIdx.x, tid = threadIdx.x, lane = tid & 31, w = tid >> 5;
  for (int i = tid; i < 4096; i += 256) sWg[i] = g_Wg[i];
  for (int i = tid; i < 384; i += 256) srP[i] = g_rP[i];
  if (tid < 64) { sbAgg[tid] = agg_b[tid]; sbg[tid] = g_bg[tid]; sA2[tid] = atti_W2[tid]; }
  __syncthreads();
  float cb = atti_b2[0];

  bool item = (bx < 64);
  int unit = item ? (bx * 8 + w) : ((bx - 64) * 8 + w);  // b or gid
  int P = item ? PP : P2;
  int u = item ? uids[unit] : u_user[unit];
  const int2* ips = reinterpret_cast<const int2*>(
      item ? (u_item + (long)unit * (PP * 2)) : (u_user_item + (long)unit * (P2 * 2)));
  float* outp = item ? (g_hiI + (long)unit * 64) : (g_hoI + (long)unit * 64);

  // stage pc for this unit into smem (per-warp row)
  sPC[w][lane] = g_uPA1[(long)u * 64 + lane];
  sPC[w][lane + 32] = g_uPA1[(long)u * 64 + 32 + lane];
  __syncwarp();

  int li = lane & 7, oct = lane >> 3;  // 8 lanes per row, 4 rows per iter
  float4 a2r0 = *reinterpret_cast<const float4*>(sA2 + li * 8);
  float4 a2r1 = *reinterpret_cast<const float4*>(sA2 + li * 8 + 4);

  float4 acca = make_float4(0.f, 0.f, 0.f, 0.f);
  float4 accb = make_float4(0.f, 0.f, 0.f, 0.f);
  float den = 0.f;
  int niter = P >> 2;  // 40->10, 100->25 (exact)
  for (int it = 0; it < niter; it++) {
    int r = it * 4 + oct;
    int2 idx = ips[r];
    float m = (idx.x > 0) ? 1.f : 0.f;
    long rid = (long)(idx.y * NI + idx.x);
    union { uint4 u4; __half2 h[4]; } tv;
    tv.u4 = *reinterpret_cast<const uint4*>(g_T2h + rid * 64 + li * 8);
    float2 t20 = __half22float2(tv.h[0]);
    float2 t21 = __half22float2(tv.h[1]);
    float2 t22 = __half22float2(tv.h[2]);
    float2 t23 = __half22float2(tv.h[3]);
    const float4* ipp = reinterpret_cast<const float4*>(g_iP + (long)idx.x * 64 + li * 8);
    float4 ipa = ipp[0], ipb = ipp[1];
    const float4* rpp = reinterpret_cast<const float4*>(srP + idx.y * 64 + li * 8);
    float4 rpa = rpp[0], rpb = rpp[1];
    const float4* pcp = reinterpret_cast<const float4*>(&sPC[w][li * 8]);
    float4 pcr0 = pcp[0], pcr1 = pcp[1];
    float s;
    s = fmaxf(fmaf(m, pcr0.x, t20.x), 0.f) * a2r0.x;
    s = fmaf(fmaxf(fmaf(m, pcr0.y, t20.y), 0.f), a2r0.y, s);
    s = fmaf(fmaxf(fmaf(m, pcr0.z, t21.x), 0.f), a2r0.z, s);
    s = fmaf(fmaxf(fmaf(m, pcr0.w, t21.y), 0.f), a2r0.w, s);
    s = fmaf(fmaxf(fmaf(m, pcr1.x, t22.x), 0.f), a2r1.x, s);
    s = fmaf(fmaxf(fmaf(m, pcr1.y, t22.y), 0.f), a2r1.y, s);
    s = fmaf(fmaxf(fmaf(m, pcr1.z, t23.x), 0.f), a2r1.z, s);
    s = fmaf(fmaxf(fmaf(m, pcr1.w, t23.y), 0.f), a2r1.w, s);
    s += __shfl_xor_sync(0xffffffffu, s, 1);
    s += __shfl_xor_sync(0xffffffffu, s, 2);
    s += __shfl_xor_sync(0xffffffffu, s, 4);
    float al = __expf(s + cb) * m;
    den += al;
    acca.x = fmaf(al, fmaxf(ipa.x + rpa.x, 0.f), acca.x);
    acca.y = fmaf(al, fmaxf(ipa.y + rpa.y, 0.f), acca.y);
    acca.z = fmaf(al, fmaxf(ipa.z + rpa.z, 0.f), acca.z);
    acca.w = fmaf(al, fmaxf(ipa.w + rpa.w, 0.f), acca.w);
    accb.x = fmaf(al, fmaxf(ipb.x + rpb.x, 0.f), accb.x);
    accb.y = fmaf(al, fmaxf(ipb.y + rpb.y, 0.f), accb.y);
    accb.z = fmaf(al, fmaxf(ipb.z + rpb.z, 0.f), accb.z);
    accb.w = fmaf(al, fmaxf(ipb.w + rpb.w, 0.f), accb.w);
  }
#pragma unroll
  for (int o = 16; o; o >>= 1) den += __shfl_xor_sync(0xffffffffu, den, o);
  den *= 0.125f;  // each row's alpha counted 8x (once per oct lane)
  float dinv = 1.f / (den + EPSF);
  float sig = den * dinv;

  // combine oct partials: sPart[w][oct][col]
  *reinterpret_cast<float4*>(&sPart[w][oct][li * 8]) = acca;
  *reinterpret_cast<float4*>(&sPart[w][oct][li * 8 + 4]) = accb;
  __syncwarp();
  int c0 = 2 * lane;
  float zx = sPart[w][0][c0] + sPart[w][1][c0] + sPart[w][2][c0] + sPart[w][3][c0];
  float zy = sPart[w][0][c0 + 1] + sPart[w][1][c0 + 1] + sPart[w][2][c0 + 1] + sPart[w][3][c0 + 1];
  sZ[w][c0] = zx * dinv;
  sZ[w][c0 + 1] = zy * dinv;
  __syncwarp();

  // epilogue GEMV: out = relu(z@Wg + sig*bg + agg_b)
  float ox = fmaf(sig, sbg[c0], sbAgg[c0]);
  float oy = fmaf(sig, sbg[c0 + 1], sbAgg[c0 + 1]);
#pragma unroll 8
  for (int k = 0; k < 64; k++) {
    float zk = sZ[w][k];
    float2 wk = *reinterpret_cast<const float2*>(sWg + k * 64 + c0);
    ox = fmaf(zk, wk.x, ox); oy = fmaf(zk, wk.y, oy);
  }
  *reinterpret_cast<float2*>(outp + c0) =
      make_float2(fmaxf(ox, 0.f), fmaxf(oy, 0.f));
}

// ---------------------------------------------------------------------------
// K2b: beta attention over q + h_iS. FFMA2 GEMM, 2 batch elements per CTA.
// ---------------------------------------------------------------------------
#define SMEM_K2B (20784 * 4)
__global__ __launch_bounds__(256) void k2b_user(
    const int* __restrict__ u_user, const float* __restrict__ user_table,
    const float* __restrict__ attu_W1, const float* __restrict__ attu_b1,
    const float* __restrict__ attu_W2, const float* __restrict__ attu_b2,
    const float* __restrict__ aggn_W, const float* __restrict__ aggn_b) {
  extern __shared__ float sm[];
  float* sU1 = sm;             float* sAggn = sm + 8192;
  float* sw2u = sm + 12288;    float* sb1u = sm + 12352;
  float* sbAggn = sm + 12416;  float* sZ = sm + 12480;
  float* sBeta = sm + 12544;   float* sRed = sm + 12584;
  float* sXT = sm + 12592;

  int tid = threadIdx.x, lane = tid & 31, w = tid >> 5;
  for (int i = tid; i < 8192; i += 256) sU1[i] = attu_W1[i];
  for (int i = tid; i < 4096; i += 256) sAggn[i] = aggn_W[i];
  if (tid < 64) { sw2u[tid] = attu_W2[tid]; sb1u[tid] = attu_b1[tid]; sbAggn[tid] = aggn_b[tid]; }
  __syncthreads();
  float cb2u = attu_b2[0];
  float* myXT = sXT + w * 1024;
  int rowbase = w * 5;

  for (int bi = 0; bi < 2; bi++) {
    int b = blockIdx.x * 2 + bi;
    __syncthreads();
    float msk[5];
#pragma unroll
    for (int j = 0; j < 5; j++) {
      int row = rowbase + j;
      int uq = u_user[b * 40 + row];
      msk[j] = (uq > 0) ? 1.f : 0.f;
      const float* hp = g_hoI + (long)(b * 40 + row) * 64;
      const float* up = user_table + (long)uq * 64;
      myXT[lane * 8 + j] = hp[lane]; myXT[(lane + 32) * 8 + j] = hp[lane + 32];
      myXT[(lane + 64) * 8 + j] = up[lane]; myXT[(lane + 96) * 8 + j] = up[lane + 32];
    }
    __syncwarp();
    float bc0 = sb1u[2 * lane], bc1 = sb1u[2 * lane + 1];
    ull a0[2], a1[2]; float s40 = bc0, s41 = bc1;
    a0[0] = a0[1] = pk2(bc0, bc0); a1[0] = a1[1] = pk2(bc1, bc1);
    wgemm2<128>(myXT, sU1, lane, a0, a1, s40, s41);
    float acc[5][2];
    unpack5(a0, a1, s40, s41, acc);
    float w0 = sw2u[2 * lane], w1 = sw2u[2 * lane + 1];
#pragma unroll
    for (int j = 0; j < 5; j++) {
      float p = fmaf(fmaxf(acc[j][0], 0.f), w0, fmaxf(acc[j][1], 0.f) * w1);
#pragma unroll
      for (int o = 16; o; o >>= 1) p += __shfl_xor_sync(0xffffffffu, p, o);
      if (lane == 0) sBeta[rowbase + j] = expf(p + cb2u) * msk[j];
    }
    __syncthreads();
    if (tid < 32) {
      float s = 0.f;
      for (int r = lane; r < 40; r += 32) s += sBeta[r];
#pragma unroll
      for (int o = 16; o; o >>= 1) s += __shfl_xor_sync(0xffffffffu, s, o);
      if (lane == 0) sRed[0] = s;
    }
    __syncthreads();
    float dinv = 1.f / (sRed[0] + EPSF);
    if (tid < 64) {
      float s = 0.f;
      for (int r = 0; r < 40; r++) s = fmaf(sBeta[r], g_hoI[(long)(b * 40 + r) * 64 + tid], s);
      sZ[tid] = s * dinv;
    }
    __syncthreads();
    if (tid < 64) {
      float s = sbAggn[tid];
      for (int k = 0; k < 64; k++) s = fmaf(sZ[k], sAggn[k * 64 + tid], s);
      g_hiS[b * 64 + tid] = fmaxf(s, 0.f);
    }
  }
}

// ---------------------------------------------------------------------------
// K3: final 3-layer combine MLP (FFMA2).
// ---------------------------------------------------------------------------
#define SMEM_K3 (24768 * 4)
__global__ __launch_bounds__(256) void k3_final(
    const float* __restrict__ cm_W1, const float* __restrict__ cm_b1,
    const float* __restrict__ cm_W2, const float* __restrict__ cm_b2,
    const float* __restrict__ cm_W3, const float* __restrict__ cm_b3,
    float* __restrict__ out) {
  extern __shared__ float sm[];
  float* sC1 = sm;          float* sC2 = sm + 8192;   float* sC3 = sm + 12288;
  float* sb1 = sm + 16384;  float* sb2 = sm + 16448;  float* sb3 = sm + 16512;
  float* sXT = sm + 16576;

  int tid = threadIdx.x, lane = tid & 31, w = tid >> 5;
  for (int i = tid; i < 8192; i += 256) sC1[i] = cm_W1[i];
  for (int i = tid; i < 4096; i += 256) { sC2[i] = cm_W2[i]; sC3[i] = cm_W3[i]; }
  if (tid < 64) { sb1[tid] = cm_b1[tid]; sb2[tid] = cm_b2[tid]; sb3[tid] = cm_b3[tid]; }
  __syncthreads();
  float* myXT = sXT + w * 1024;
  int rowbase = blockIdx.x * 40 + w * 5;
#pragma unroll
  for (int j = 0; j < 5; j++) {
    int row = rowbase + j;
    float x0 = 0, x1 = 0, x2 = 0, x3 = 0;
    if (row < BB) {
      x0 = g_hiI[row * 64 + lane]; x1 = g_hiI[row * 64 + 32 + lane];
      x2 = g_hiS[row * 64 + lane]; x3 = g_hiS[row * 64 + 32 + lane];
    }
    myXT[lane * 8 + j] = x0; myXT[(lane + 32) * 8 + j] = x1;
    myXT[(lane + 64) * 8 + j] = x2; myXT[(lane + 96) * 8 + j] = x3;
  }
  __syncwarp();
  float acc[5][2];
  {
    float bc0 = sb1[2 * lane], bc1 = sb1[2 * lane + 1];
    ull a0[2], a1[2]; float s40 = bc0, s41 = bc1;
    a0[0] = a0[1] = pk2(bc0, bc0); a1[0] = a1[1] = pk2(bc1, bc1);
    wgemm2<128>(myXT, sC1, lane, a0, a1, s40, s41);
    unpack5(a0, a1, s40, s41, acc);
  }
#pragma unroll
  for (int j = 0; j < 5; j++) { acc[j][0] = fmaxf(acc[j][0], 0.f); acc[j][1] = fmaxf(acc[j][1], 0.f); }
  __syncwarp(); wtrans(myXT, lane, acc); __syncwarp();
  {
    float bc0 = sb2[2 * lane], bc1 = sb2[2 * lane + 1];
    ull a0[2], a1[2]; float s40 = bc0, s41 = bc1;
    a0[0] = a0[1] = pk2(bc0, bc0); a1[0] = a1[1] = pk2(bc1, bc1);
    wgemm2<64>(myXT, sC2, lane, a0, a1, s40, s41);
    unpack5(a0, a1, s40, s41, acc);
  }
#pragma unroll
  for (int j = 0; j < 5; j++) { acc[j][0] = fmaxf(acc[j][0], 0.f); acc[j][1] = fmaxf(acc[j][1], 0.f); }
  __syncwarp(); wtrans(myXT, lane, acc); __syncwarp();
  {
    float bc0 = sb3[2 * lane], bc1 = sb3[2 * lane + 1];
    ull a0[2], a1[2]; float s40 = bc0, s41 = bc1;
    a0[0] = a0[1] = pk2(bc0, bc0); a1[0] = a1[1] = pk2(bc1, bc1);
    wgemm2<64>(myXT, sC3, lane, a0, a1, s40, s41);
    unpack5(a0, a1, s40, s41, acc);
  }
#pragma unroll
  for (int j = 0; j < 5; j++) {
    int row = rowbase + j;
    if (row < BB) {
      out[row * 64 + 2 * lane]     = fmaxf(acc[j][0], 0.f);
      out[row * 64 + 2 * lane + 1] = fmaxf(acc[j][1], 0.f);
    }
  }
}

// ---------------------------------------------------------------------------
extern "C" void kernel_launch(void* const* d_in, const int* in_sizes, int n_in,
                              void* d_out, int out_size) {
  const int* uids        = (const int*)d_in[0];
  const int* u_item      = (const int*)d_in[1];
  const int* u_user      = (const int*)d_in[2];
  const int* u_user_item = (const int*)d_in[3];
  const float* user_table = (const float*)d_in[4];
  const float* item_table = (const float*)d_in[5];
  const float* rate_table = (const float*)d_in[6];
  const float* gv_W1 = (const float*)d_in[7];   const float* gv_b1 = (const float*)d_in[8];
  const float* gv_W2 = (const float*)d_in[9];   const float* gv_b2 = (const float*)d_in[10];
  const float* atti_W1 = (const float*)d_in[11]; const float* atti_b1 = (const float*)d_in[12];
  const float* atti_W2 = (const float*)d_in[13]; const float* atti_b2 = (const float*)d_in[14];
  const float* agg_W = (const float*)d_in[15];   const float* agg_b = (const float*)d_in[16];
  const float* attu_W1 = (const float*)d_in[17]; const float* attu_b1 = (const float*)d_in[18];
  const float* attu_W2 = (const float*)d_in[19]; const float* attu_b2 = (const float*)d_in[20];
  const float* aggn_W = (const float*)d_in[21];  const float* aggn_b = (const float*)d_in[22];
  const float* cm_W1 = (const float*)d_in[23];   const float* cm_b1 = (const float*)d_in[24];
  const float* cm_W2 = (const float*)d_in[25];   const float* cm_b2 = (const float*)d_in[26];
  const float* cm_W3 = (const float*)d_in[27];   const float* cm_b3 = (const float*)d_in[28];
  float* out = (float*)d_out;

  cudaFuncSetAttribute(k0_proj,  cudaFuncAttributeMaxDynamicSharedMemorySize, SMEM_K0P);
  cudaFuncSetAttribute(k0_combo, cudaFuncAttributeMaxDynamicSharedMemorySize, SMEM_K0C);
  cudaFuncSetAttribute(k2b_user, cudaFuncAttributeMaxDynamicSharedMemorySize, SMEM_K2B);
  cudaFuncSetAttribute(k3_final, cudaFuncAttributeMaxDynamicSharedMemorySize, SMEM_K3);

  k0_pre<<<33, 256>>>(rate_table, gv_W1, gv_b1, gv_W2, gv_b2, atti_W1, atti_b1, agg_W);
  k0_proj<<<500, 256, SMEM_K0P>>>(item_table, user_table, gv_W1, atti_W1);
  k0_combo<<<1875, 256, SMEM_K0C>>>();
  k2s1_attn<<<64 + 2560, 256>>>(uids, u_user, u_user_item, u_item,
                                agg_b, atti_W2, atti_b2);
  k2b_user<<<256, 256, SMEM_K2B>>>(u_user, user_table, attu_W1, attu_b1, attu_W2,
                                   attu_b2, aggn_W, aggn_b);
  k3_final<<<13, 256, SMEM_K3>>>(cm_W1, cm_b1, cm_W2, cm_b2, cm_W3, cm_b3, out);
}

// round 14
// speedup vs baseline: 1.0598x; 1.0070x over previous
#include <cuda_runtime.h>
#include <cuda_fp16.h>

#define EPSF 1e-10f
#define NI 100000
#define NU 100000
#define NR 6
#define BB 512
#define PP 100
#define QQ 40
#define P2 40
#define XS 12  // XT row stride (floats)

typedef unsigned long long ull;

// ---------------- persistent scratch (static device memory) -----------------
__device__ float g_iP[NI * 64];             // item_table @ W1_top (fp32, for combo)
__device__ __half g_iPh[NI * 64];           // fp16 shadow for k2s1 phase B
__device__ float g_uPA1[NU * 64];           // user_table @ A1_bot
__device__ float g_rP[NR * 64];             // rate_table @ W1_bot + gv_b1
__device__ float g_Wf[64 * 64];             // W2 @ A1_top
__device__ float g_bf[64];                  // b2 @ A1_top + b1a
__device__ float g_Wg[64 * 64];             // W2 @ agg_W
__device__ float g_bg[64];                  // b2 @ agg_W
__device__ __half g_T2h[(long)NR * NI * 64]; // T2 (fp16) per (rate,item)
__device__ float g_hoI[BB * QQ * 64];
__device__ float g_hiI[BB * 64];
__device__ float g_hiS[BB * 64];

// ------------------------- f32x2 packed helpers ----------------------------
__device__ __forceinline__ ull pk2(float lo, float hi) {
  ull r; asm("mov.b64 %0, {%1,%2};" : "=l"(r) : "f"(lo), "f"(hi)); return r;
}
__device__ __forceinline__ void fma2(ull& d, ull a, ull b) {
  asm("fma.rn.f32x2 %0, %1, %2, %0;" : "+l"(d) : "l"(a), "l"(b));
}
__device__ __forceinline__ void upk(ull v, float& lo, float& hi) {
  asm("mov.b64 {%0,%1}, %2;" : "=f"(lo), "=f"(hi) : "l"(v));
}

// ---------------------------------------------------------------------------
// packed 5-row warp GEMM (XT stride 8)
// ---------------------------------------------------------------------------
template <int K>
__device__ __forceinline__ void wgemm2(const float* __restrict__ sXT,
                                       const float* __restrict__ sW, int lane,
                                       ull a0[2], ull a1[2], float& s40, float& s41) {
#pragma unroll 8
  for (int k = 0; k < K; k++) {
    ulonglong2 xu = *reinterpret_cast<const ulonglong2*>(sXT + k * 8); // rows 0..3
    float x5 = sXT[k * 8 + 4];
    float2 wv = *reinterpret_cast<const float2*>(sW + k * 64 + 2 * lane);
    ull w0 = pk2(wv.x, wv.x), w1 = pk2(wv.y, wv.y);
    fma2(a0[0], xu.x, w0); fma2(a1[0], xu.x, w1);
    fma2(a0[1], xu.y, w0); fma2(a1[1], xu.y, w1);
    s40 = fmaf(x5, wv.x, s40); s41 = fmaf(x5, wv.y, s41);
  }
}
__device__ __forceinline__ void unpack5(const ull a0[2], const ull a1[2],
                                        float s40, float s41, float acc[5][2]) {
  upk(a0[0], acc[0][0], acc[1][0]); upk(a0[1], acc[2][0], acc[3][0]);
  upk(a1[0], acc[0][1], acc[1][1]); upk(a1[1], acc[2][1], acc[3][1]);
  acc[4][0] = s40; acc[4][1] = s41;
}
__device__ __forceinline__ void wtrans(float* sT, int lane, const float acc[5][2]) {
#pragma unroll
  for (int j = 0; j < 5; j++) {
    sT[(2 * lane) * 8 + j]     = acc[j][0];
    sT[(2 * lane + 1) * 8 + j] = acc[j][1];
  }
}

// ---------------------------------------------------------------------------
// K0_pre (parallel): grid 33.
// ---------------------------------------------------------------------------
__global__ __launch_bounds__(256) void k0_pre(
    const float* __restrict__ rate_table, const float* __restrict__ gv_W1,
    const float* __restrict__ gv_b1, const float* __restrict__ gv_W2,
    const float* __restrict__ gv_b2, const float* __restrict__ atti_W1,
    const float* __restrict__ atti_b1, const float* __restrict__ agg_W) {
  int b = blockIdx.x, t = threadIdx.x;
  if (b < 16) {
    int idx = b * 256 + t;
    int k = idx >> 6, c = idx & 63;
    float s = 0.f;
#pragma unroll 8
    for (int j = 0; j < 64; j++) s = fmaf(gv_W2[k * 64 + j], atti_W1[j * 64 + c], s);
    g_Wf[idx] = s;
  } else if (b < 32) {
    int idx = (b - 16) * 256 + t;
    int k = idx >> 6, c = idx & 63;
    float s = 0.f;
#pragma unroll 8
    for (int j = 0; j < 64; j++) s = fmaf(gv_W2[k * 64 + j], agg_W[j * 64 + c], s);
    g_Wg[idx] = s;
  } else {
    for (int i = t; i < NR * 64; i += 256) {
      int r = i >> 6, c = i & 63;
      float s = gv_b1[c];
      const float* W1b = gv_W1 + 4096;
#pragma unroll 8
      for (int k = 0; k < 64; k++) s = fmaf(rate_table[r * 64 + k], W1b[k * 64 + c], s);
      g_rP[i] = s;
    }
    if (t < 64) {
      float s = atti_b1[t], sg = 0.f;
#pragma unroll 8
      for (int j = 0; j < 64; j++) {
        s = fmaf(gv_b2[j], atti_W1[j * 64 + t], s);
        sg = fmaf(gv_b2[j], agg_W[j * 64 + t], sg);
      }
      g_bf[t] = s;
      g_bg[t] = sg;
    }
  }
}

// ---------------------------------------------------------------------------
// K0_proj (FFMA2, packed x loads; also emits fp16 shadow of g_iP)
// ---------------------------------------------------------------------------
#define SMEM_K0P ((4096 + 4096 + 8 * 64 * XS) * 4)
__global__ __launch_bounds__(256) void k0_proj(
    const float* __restrict__ item_table, const float* __restrict__ user_table,
    const float* __restrict__ gv_W1, const float* __restrict__ atti_W1) {
  extern __shared__ float sm[];
  float* sWa = sm;
  float* sWb = sm + 4096;
  float* sXT = sm + 8192;

  int tid = threadIdx.x, lane = tid & 31, w = tid >> 5;
  for (int i = tid; i < 4096; i += 256) { sWa[i] = gv_W1[i]; sWb[i] = atti_W1[4096 + i]; }
  __syncthreads();
  float* myXT = sXT + w * (64 * XS);

  for (int it = 0; it < 5; it++) {
    int rid0 = blockIdx.x * 400 + it * 80 + w * 10;
    bool half2b = (rid0 >= NI);
    const float* src = half2b ? user_table : item_table;
    const float* sW = half2b ? sWb : sWa;
    float* dst = half2b ? g_uPA1 : g_iP;
    int base = half2b ? (rid0 - NI) : rid0;
#pragma unroll
    for (int j = 0; j < 10; j++) {
      const float* sp = src + (long)(base + j) * 64;
      myXT[lane * XS + j] = sp[lane];
      myXT[(lane + 32) * XS + j] = sp[lane + 32];
    }
    __syncwarp();
    ull a0[5], a1[5];
#pragma unroll
    for (int p = 0; p < 5; p++) { a0[p] = 0ull; a1[p] = 0ull; }
#pragma unroll 8
    for (int k = 0; k < 64; k++) {
      ulonglong2 xu0 = *reinterpret_cast<const ulonglong2*>(myXT + k * XS);
      ulonglong2 xu1 = *reinterpret_cast<const ulonglong2*>(myXT + k * XS + 4);
      ull xp4 = *reinterpret_cast<const ull*>(myXT + k * XS + 8);
      float2 wv = *reinterpret_cast<const float2*>(sW + k * 64 + 2 * lane);
      ull w0 = pk2(wv.x, wv.x), w1 = pk2(wv.y, wv.y);
      fma2(a0[0], xu0.x, w0); fma2(a1[0], xu0.x, w1);
      fma2(a0[1], xu0.y, w0); fma2(a1[1], xu0.y, w1);
      fma2(a0[2], xu1.x, w0); fma2(a1[2], xu1.x, w1);
      fma2(a0[3], xu1.y, w0); fma2(a1[3], xu1.y, w1);
      fma2(a0[4], xp4, w0);   fma2(a1[4], xp4, w1);
    }
#pragma unroll
    for (int p = 0; p < 5; p++) {
      float r0c0, r1c0, r0c1, r1c1;
      upk(a0[p], r0c0, r1c0); upk(a1[p], r0c1, r1c1);
      long o0 = (long)(base + 2 * p) * 64 + 2 * lane;
      long o1 = (long)(base + 2 * p + 1) * 64 + 2 * lane;
      *reinterpret_cast<float2*>(dst + o0) = make_float2(r0c0, r0c1);
      *reinterpret_cast<float2*>(dst + o1) = make_float2(r1c0, r1c1);
      if (!half2b) {
        *reinterpret_cast<__half2*>(g_iPh + o0) = __floats2half2_rn(r0c0, r0c1);
        *reinterpret_cast<__half2*>(g_iPh + o1) = __floats2half2_rn(r1c0, r1c1);
      }
    }
    __syncwarp();
  }
}

// ---------------------------------------------------------------------------
// K0_combo (FFMA2, single GEMM, fp16 T2 output)
// ---------------------------------------------------------------------------
#define SMEM_K0C ((4096 + 8 * 64 * XS + 384 + 64) * 4)
__global__ __launch_bounds__(256) void k0_combo() {
  extern __shared__ float sm[];
  float* sWf = sm;                  // 4096
  float* sXT = sm + 4096;           // 6144
  float* srP = sm + 4096 + 6144;    // 384
  float* sbf = srP + 384;           // 64

  int tid = threadIdx.x, lane = tid & 31, w = tid >> 5;
  for (int i = tid; i < 4096; i += 256) sWf[i] = g_Wf[i];
  for (int i = tid; i < 384; i += 256) srP[i] = g_rP[i];
  if (tid < 64) sbf[tid] = g_bf[tid];
  __syncthreads();
  float* myXT = sXT + w * (64 * XS);

  float2 bb2 = *reinterpret_cast<const float2*>(sbf + 2 * lane);
  ull b20 = pk2(bb2.x, bb2.x), b21 = pk2(bb2.y, bb2.y);

  for (int it = 0; it < 4; it++) {
    int rid0 = blockIdx.x * 320 + it * 80 + w * 10;
    int r = rid0 / NI;
    int i0 = rid0 - r * NI;
    const float* rp = srP + r * 64;
    float rp0 = rp[lane], rp1 = rp[lane + 32];
#pragma unroll
    for (int j = 0; j < 10; j++) {
      const float* ip = g_iP + (long)(i0 + j) * 64;
      myXT[lane * XS + j] = fmaxf(ip[lane] + rp0, 0.f);
      myXT[(lane + 32) * XS + j] = fmaxf(ip[lane + 32] + rp1, 0.f);
    }
    __syncwarp();
    ull a20[5], a21[5];
#pragma unroll
    for (int p = 0; p < 5; p++) { a20[p] = b20; a21[p] = b21; }
#pragma unroll 8
    for (int k = 0; k < 64; k++) {
      ulonglong2 xu0 = *reinterpret_cast<const ulonglong2*>(myXT + k * XS);
      ulonglong2 xu1 = *reinterpret_cast<const ulonglong2*>(myXT + k * XS + 4);
      ull xp4 = *reinterpret_cast<const ull*>(myXT + k * XS + 8);
      float2 w2v = *reinterpret_cast<const float2*>(sWf + k * 64 + 2 * lane);
      ull w20 = pk2(w2v.x, w2v.x), w21 = pk2(w2v.y, w2v.y);
      fma2(a20[0], xu0.x, w20); fma2(a21[0], xu0.x, w21);
      fma2(a20[1], xu0.y, w20); fma2(a21[1], xu0.y, w21);
      fma2(a20[2], xu1.x, w20); fma2(a21[2], xu1.x, w21);
      fma2(a20[3], xu1.y, w20); fma2(a21[3], xu1.y, w21);
      fma2(a20[4], xp4, w20);   fma2(a21[4], xp4, w21);
    }
#pragma unroll
    for (int p = 0; p < 5; p++) {
      float r0c0, r1c0, r0c1, r1c1;
      upk(a20[p], r0c0, r1c0); upk(a21[p], r0c1, r1c1);
      long o0 = (long)(rid0 + 2 * p) * 64 + 2 * lane;
      long o1 = (long)(rid0 + 2 * p + 1) * 64 + 2 * lane;
      *reinterpret_cast<__half2*>(g_T2h + o0) = __floats2half2_rn(r0c0, r0c1);
      *reinterpret_cast<__half2*>(g_T2h + o1) = __floats2half2_rn(r1c0, r1c1);
    }
    __syncwarp();
  }
}

// ---------------------------------------------------------------------------
// K2s1: merged attention kernel, fused oct-slice, fp16 T2 + fp16 iP gathers.
// blocks [0,64): item; [64, 64+2560): social.
// ---------------------------------------------------------------------------
__global__ __launch_bounds__(256, 5) void k2s1_attn(
    const int* __restrict__ uids,
    const int* __restrict__ u_user, const int* __restrict__ u_user_item,
    const int* __restrict__ u_item,
    const float* __restrict__ agg_b,
    const float* __restrict__ atti_W2, const float* __restrict__ atti_b2) {
  __shared__ float sWg[4096];
  __shared__ float srP[384];
  __shared__ float sbAgg[64];
  __shared__ float sbg[64];
  __shared__ float sA2[64];
  __shared__ float sPC[8][64];
  __shared__ float sPart[8][4][64];   // [warp][oct][col]
  __shared__ float sZ[8][64];

  int bx = blockIdx.x, tid = threadIdx.x, lane = tid & 31, w = tid >> 5;
  for (int i = tid; i < 4096; i += 256) sWg[i] = g_Wg[i];
  for (int i = tid; i < 384; i += 256) srP[i] = g_rP[i];
  if (tid < 64) { sbAgg[tid] = agg_b[tid]; sbg[tid] = g_bg[tid]; sA2[tid] = atti_W2[tid]; }
  __syncthreads();
  float cb = atti_b2[0];

  bool item = (bx < 64);
  int unit = item ? (bx * 8 + w) : ((bx - 64) * 8 + w);  // b or gid
  int P = item ? PP : P2;
  int u = item ? uids[unit] : u_user[unit];
  const int2* ips = reinterpret_cast<const int2*>(
      item ? (u_item + (long)unit * (PP * 2)) : (u_user_item + (long)unit * (P2 * 2)));
  float* outp = item ? (g_hiI + (long)unit * 64) : (g_hoI + (long)unit * 64);

  // stage pc for this unit into smem (per-warp row)
  sPC[w][lane] = g_uPA1[(long)u * 64 + lane];
  sPC[w][lane + 32] = g_uPA1[(long)u * 64 + 32 + lane];
  __syncwarp();

  int li = lane & 7, oct = lane >> 3;  // 8 lanes per row, 4 rows per iter
  float4 a2r0 = *reinterpret_cast<const float4*>(sA2 + li * 8);
  float4 a2r1 = *reinterpret_cast<const float4*>(sA2 + li * 8 + 4);

  float4 acca = make_float4(0.f, 0.f, 0.f, 0.f);
  float4 accb = make_float4(0.f, 0.f, 0.f, 0.f);
  float den = 0.f;
  int niter = P >> 2;  // 40->10, 100->25 (exact)
  for (int it = 0; it < niter; it++) {
    int r = it * 4 + oct;
    int2 idx = ips[r];
    float m = (idx.x > 0) ? 1.f : 0.f;
    long rid = (long)(idx.y * NI + idx.x);
    union { uint4 u4; __half2 h[4]; } tv;
    tv.u4 = *reinterpret_cast<const uint4*>(g_T2h + rid * 64 + li * 8);
    float2 t20 = __half22float2(tv.h[0]);
    float2 t21 = __half22float2(tv.h[1]);
    float2 t22 = __half22float2(tv.h[2]);
    float2 t23 = __half22float2(tv.h[3]);
    union { uint4 u4; __half2 h[4]; } iv;
    iv.u4 = *reinterpret_cast<const uint4*>(g_iPh + (long)idx.x * 64 + li * 8);
    float2 ip0 = __half22float2(iv.h[0]);
    float2 ip1 = __half22float2(iv.h[1]);
    float2 ip2 = __half22float2(iv.h[2]);
    float2 ip3 = __half22float2(iv.h[3]);
    const float4* rpp = reinterpret_cast<const float4*>(srP + idx.y * 64 + li * 8);
    float4 rpa = rpp[0], rpb = rpp[1];
    const float4* pcp = reinterpret_cast<const float4*>(&sPC[w][li * 8]);
    float4 pcr0 = pcp[0], pcr1 = pcp[1];
    float s;
    s = fmaxf(fmaf(m, pcr0.x, t20.x), 0.f) * a2r0.x;
    s = fmaf(fmaxf(fmaf(m, pcr0.y, t20.y), 0.f), a2r0.y, s);
    s = fmaf(fmaxf(fmaf(m, pcr0.z, t21.x), 0.f), a2r0.z, s);
    s = fmaf(fmaxf(fmaf(m, pcr0.w, t21.y), 0.f), a2r0.w, s);
    s = fmaf(fmaxf(fmaf(m, pcr1.x, t22.x), 0.f), a2r1.x, s);
    s = fmaf(fmaxf(fmaf(m, pcr1.y, t22.y), 0.f), a2r1.y, s);
    s = fmaf(fmaxf(fmaf(m, pcr1.z, t23.x), 0.f), a2r1.z, s);
    s = fmaf(fmaxf(fmaf(m, pcr1.w, t23.y), 0.f), a2r1.w, s);
    s += __shfl_xor_sync(0xffffffffu, s, 1);
    s += __shfl_xor_sync(0xffffffffu, s, 2);
    s += __shfl_xor_sync(0xffffffffu, s, 4);
    float al = __expf(s + cb) * m;
    den += al;
    acca.x = fmaf(al, fmaxf(ip0.x + rpa.x, 0.f), acca.x);
    acca.y = fmaf(al, fmaxf(ip0.y + rpa.y, 0.f), acca.y);
    acca.z = fmaf(al, fmaxf(ip1.x + rpa.z, 0.f), acca.z);
    acca.w = fmaf(al, fmaxf(ip1.y + rpa.w, 0.f), acca.w);
    accb.x = fmaf(al, fmaxf(ip2.x + rpb.x, 0.f), accb.x);
    accb.y = fmaf(al, fmaxf(ip2.y + rpb.y, 0.f), accb.y);
    accb.z = fmaf(al, fmaxf(ip3.x + rpb.z, 0.f), accb.z);
    accb.w = fmaf(al, fmaxf(ip3.y + rpb.w, 0.f), accb.w);
  }
#pragma unroll
  for (int o = 16; o; o >>= 1) den += __shfl_xor_sync(0xffffffffu, den, o);
  den *= 0.125f;  // each row's alpha counted 8x (once per oct lane)
  float dinv = 1.f / (den + EPSF);
  float sig = den * dinv;

  // combine oct partials: sPart[w][oct][col]
  *reinterpret_cast<float4*>(&sPart[w][oct][li * 8]) = acca;
  *reinterpret_cast<float4*>(&sPart[w][oct][li * 8 + 4]) = accb;
  __syncwarp();
  int c0 = 2 * lane;
  float zx = sPart[w][0][c0] + sPart[w][1][c0] + sPart[w][2][c0] + sPart[w][3][c0];
  float zy = sPart[w][0][c0 + 1] + sPart[w][1][c0 + 1] + sPart[w][2][c0 + 1] + sPart[w][3][c0 + 1];
  sZ[w][c0] = zx * dinv;
  sZ[w][c0 + 1] = zy * dinv;
  __syncwarp();

  // epilogue GEMV: out = relu(z@Wg + sig*bg + agg_b)
  float ox = fmaf(sig, sbg[c0], sbAgg[c0]);
  float oy = fmaf(sig, sbg[c0 + 1], sbAgg[c0 + 1]);
#pragma unroll 8
  for (int k = 0; k < 64; k++) {
    float zk = sZ[w][k];
    float2 wk = *reinterpret_cast<const float2*>(sWg + k * 64 + c0);
    ox = fmaf(zk, wk.x, ox); oy = fmaf(zk, wk.y, oy);
  }
  *reinterpret_cast<float2*>(outp + c0) =
      make_float2(fmaxf(ox, 0.f), fmaxf(oy, 0.f));
}

// ---------------------------------------------------------------------------
// K2b: beta attention over q + h_iS. FFMA2 GEMM, 2 batch elements per CTA.
// ---------------------------------------------------------------------------
#define SMEM_K2B (20784 * 4)
__global__ __launch_bounds__(256) void k2b_user(
    const int* __restrict__ u_user, const float* __restrict__ user_table,
    const float* __restrict__ attu_W1, const float* __restrict__ attu_b1,
    const float* __restrict__ attu_W2, const float* __restrict__ attu_b2,
    const float* __restrict__ aggn_W, const float* __restrict__ aggn_b) {
  extern __shared__ float sm[];
  float* sU1 = sm;             float* sAggn = sm + 8192;
  float* sw2u = sm + 12288;    float* sb1u = sm + 12352;
  float* sbAggn = sm + 12416;  float* sZ = sm + 12480;
  float* sBeta = sm + 12544;   float* sRed = sm + 12584;
  float* sXT = sm + 12592;

  int tid = threadIdx.x, lane = tid & 31, w = tid >> 5;
  for (int i = tid; i < 8192; i += 256) sU1[i] = attu_W1[i];
  for (int i = tid; i < 4096; i += 256) sAggn[i] = aggn_W[i];
  if (tid < 64) { sw2u[tid] = attu_W2[tid]; sb1u[tid] = attu_b1[tid]; sbAggn[tid] = aggn_b[tid]; }
  __syncthreads();
  float cb2u = attu_b2[0];
  float* myXT = sXT + w * 1024;
  int rowbase = w * 5;

  for (int bi = 0; bi < 2; bi++) {
    int b = blockIdx.x * 2 + bi;
    __syncthreads();
    float msk[5];
#pragma unroll
    for (int j = 0; j < 5; j++) {
      int row = rowbase + j;
      int uq = u_user[b * 40 + row];
      msk[j] = (uq > 0) ? 1.f : 0.f;
      const float* hp = g_hoI + (long)(b * 40 + row) * 64;
      const float* up = user_table + (long)uq * 64;
      myXT[lane * 8 + j] = hp[lane]; myXT[(lane + 32) * 8 + j] = hp[lane + 32];
      myXT[(lane + 64) * 8 + j] = up[lane]; myXT[(lane + 96) * 8 + j] = up[lane + 32];
    }
    __syncwarp();
    float bc0 = sb1u[2 * lane], bc1 = sb1u[2 * lane + 1];
    ull a0[2], a1[2]; float s40 = bc0, s41 = bc1;
    a0[0] = a0[1] = pk2(bc0, bc0); a1[0] = a1[1] = pk2(bc1, bc1);
    wgemm2<128>(myXT, sU1, lane, a0, a1, s40, s41);
    float acc[5][2];
    unpack5(a0, a1, s40, s41, acc);
    float w0 = sw2u[2 * lane], w1 = sw2u[2 * lane + 1];
#pragma unroll
    for (int j = 0; j < 5; j++) {
      float p = fmaf(fmaxf(acc[j][0], 0.f), w0, fmaxf(acc[j][1], 0.f) * w1);
#pragma unroll
      for (int o = 16; o; o >>= 1) p += __shfl_xor_sync(0xffffffffu, p, o);
      if (lane == 0) sBeta[rowbase + j] = expf(p + cb2u) * msk[j];
    }
    __syncthreads();
    if (tid < 32) {
      float s = 0.f;
      for (int r = lane; r < 40; r += 32) s += sBeta[r];
#pragma unroll
      for (int o = 16; o; o >>= 1) s += __shfl_xor_sync(0xffffffffu, s, o);
      if (lane == 0) sRed[0] = s;
    }
    __syncthreads();
    float dinv = 1.f / (sRed[0] + EPSF);
    if (tid < 64) {
      float s = 0.f;
      for (int r = 0; r < 40; r++) s = fmaf(sBeta[r], g_hoI[(long)(b * 40 + r) * 64 + tid], s);
      sZ[tid] = s * dinv;
    }
    __syncthreads();
    if (tid < 64) {
      float s = sbAggn[tid];
      for (int k = 0; k < 64; k++) s = fmaf(sZ[k], sAggn[k * 64 + tid], s);
      g_hiS[b * 64 + tid] = fmaxf(s, 0.f);
    }
  }
}

// ---------------------------------------------------------------------------
// K3: final 3-layer combine MLP (FFMA2).
// ---------------------------------------------------------------------------
#define SMEM_K3 (24768 * 4)
__global__ __launch_bounds__(256) void k3_final(
    const float* __restrict__ cm_W1, const float* __restrict__ cm_b1,
    const float* __restrict__ cm_W2, const float* __restrict__ cm_b2,
    const float* __restrict__ cm_W3, const float* __restrict__ cm_b3,
    float* __restrict__ out) {
  extern __shared__ float sm[];
  float* sC1 = sm;          float* sC2 = sm + 8192;   float* sC3 = sm + 12288;
  float* sb1 = sm + 16384;  float* sb2 = sm + 16448;  float* sb3 = sm + 16512;
  float* sXT = sm + 16576;

  int tid = threadIdx.x, lane = tid & 31, w = tid >> 5;
  for (int i = tid; i < 8192; i += 256) sC1[i] = cm_W1[i];
  for (int i = tid; i < 4096; i += 256) { sC2[i] = cm_W2[i]; sC3[i] = cm_W3[i]; }
  if (tid < 64) { sb1[tid] = cm_b1[tid]; sb2[tid] = cm_b2[tid]; sb3[tid] = cm_b3[tid]; }
  __syncthreads();
  float* myXT = sXT + w * 1024;
  int rowbase = blockIdx.x * 40 + w * 5;
#pragma unroll
  for (int j = 0; j < 5; j++) {
    int row = rowbase + j;
    float x0 = 0, x1 = 0, x2 = 0, x3 = 0;
    if (row < BB) {
      x0 = g_hiI[row * 64 + lane]; x1 = g_hiI[row * 64 + 32 + lane];
      x2 = g_hiS[row * 64 + lane]; x3 = g_hiS[row * 64 + 32 + lane];
    }
    myXT[lane * 8 + j] = x0; myXT[(lane + 32) * 8 + j] = x1;
    myXT[(lane + 64) * 8 + j] = x2; myXT[(lane + 96) * 8 + j] = x3;
  }
  __syncwarp();
  float acc[5][2];
  {
    float bc0 = sb1[2 * lane], bc1 = sb1[2 * lane + 1];
    ull a0[2], a1[2]; float s40 = bc0, s41 = bc1;
    a0[0] = a0[1] = pk2(bc0, bc0); a1[0] = a1[1] = pk2(bc1, bc1);
    wgemm2<128>(myXT, sC1, lane, a0, a1, s40, s41);
    unpack5(a0, a1, s40, s41, acc);
  }
#pragma unroll
  for (int j = 0; j < 5; j++) { acc[j][0] = fmaxf(acc[j][0], 0.f); acc[j][1] = fmaxf(acc[j][1], 0.f); }
  __syncwarp(); wtrans(myXT, lane, acc); __syncwarp();
  {
    float bc0 = sb2[2 * lane], bc1 = sb2[2 * lane + 1];
    ull a0[2], a1[2]; float s40 = bc0, s41 = bc1;
    a0[0] = a0[1] = pk2(bc0, bc0); a1[0] = a1[1] = pk2(bc1, bc1);
    wgemm2<64>(myXT, sC2, lane, a0, a1, s40, s41);
    unpack5(a0, a1, s40, s41, acc);
  }
#pragma unroll
  for (int j = 0; j < 5; j++) { acc[j][0] = fmaxf(acc[j][0], 0.f); acc[j][1] = fmaxf(acc[j][1], 0.f); }
  __syncwarp(); wtrans(myXT, lane, acc); __syncwarp();
  {
    float bc0 = sb3[2 * lane], bc1 = sb3[2 * lane + 1];
    ull a0[2], a1[2]; float s40 = bc0, s41 = bc1;
    a0[0] = a0[1] = pk2(bc0, bc0); a1[0] = a1[1] = pk2(bc1, bc1);
    wgemm2<64>(myXT, sC3, lane, a0, a1, s40, s41);
    unpack5(a0, a1, s40, s41, acc);
  }
#pragma unroll
  for (int j = 0; j < 5; j++) {
    int row = rowbase + j;
    if (row < BB) {
      out[row * 64 + 2 * lane]     = fmaxf(acc[j][0], 0.f);
      out[row * 64 + 2 * lane + 1] = fmaxf(acc[j][1], 0.f);
    }
  }
}

// ---------------------------------------------------------------------------
extern "C" void kernel_launch(void* const* d_in, const int* in_sizes, int n_in,
                              void* d_out, int out_size) {
  const int* uids        = (const int*)d_in[0];
  const int* u_item      = (const int*)d_in[1];
  const int* u_user      = (const int*)d_in[2];
  const int* u_user_item = (const int*)d_in[3];
  const float* user_table = (const float*)d_in[4];
  const float* item_table = (const float*)d_in[5];
  const float* rate_table = (const float*)d_in[6];
  const float* gv_W1 = (const float*)d_in[7];   const float* gv_b1 = (const float*)d_in[8];
  const float* gv_W2 = (const float*)d_in[9];   const float* gv_b2 = (const float*)d_in[10];
  const float* atti_W1 = (const float*)d_in[11]; const float* atti_b1 = (const float*)d_in[12];
  const float* atti_W2 = (const float*)d_in[13]; const float* atti_b2 = (const float*)d_in[14];
  const float* agg_W = (const float*)d_in[15];   const float* agg_b = (const float*)d_in[16];
  const float* attu_W1 = (const float*)d_in[17]; const float* attu_b1 = (const float*)d_in[18];
  const float* attu_W2 = (const float*)d_in[19]; const float* attu_b2 = (const float*)d_in[20];
  const float* aggn_W = (const float*)d_in[21];  const float* aggn_b = (const float*)d_in[22];
  const float* cm_W1 = (const float*)d_in[23];   const float* cm_b1 = (const float*)d_in[24];
  const float* cm_W2 = (const float*)d_in[25];   const float* cm_b2 = (const float*)d_in[26];
  const float* cm_W3 = (const float*)d_in[27];   const float* cm_b3 = (const float*)d_in[28];
  float* out = (float*)d_out;

  cudaFuncSetAttribute(k0_proj,  cudaFuncAttributeMaxDynamicSharedMemorySize, SMEM_K0P);
  cudaFuncSetAttribute(k0_combo, cudaFuncAttributeMaxDynamicSharedMemorySize, SMEM_K0C);
  cudaFuncSetAttribute(k2b_user, cudaFuncAttributeMaxDynamicSharedMemorySize, SMEM_K2B);
  cudaFuncSetAttribute(k3_final, cudaFuncAttributeMaxDynamicSharedMemorySize, SMEM_K3);

  k0_pre<<<33, 256>>>(rate_table, gv_W1, gv_b1, gv_W2, gv_b2, atti_W1, atti_b1, agg_W);
  k0_proj<<<500, 256, SMEM_K0P>>>(item_table, user_table, gv_W1, atti_W1);
  k0_combo<<<1875, 256, SMEM_K0C>>>();
  k2s1_attn<<<64 + 2560, 256>>>(uids, u_user, u_user_item, u_item,
                                agg_b, atti_W2, atti_b2);
  k2b_user<<<256, 256, SMEM_K2B>>>(u_user, user_table, attu_W1, attu_b1, attu_W2,
                                   attu_b2, aggn_W, aggn_b);
  k3_final<<<13, 256, SMEM_K3>>>(cm_W1, cm_b1, cm_W2, cm_b2, cm_W3, cm_b3, out);
}

// round 17
// speedup vs baseline: 1.0964x; 1.0346x over previous
#include <cuda_runtime.h>
#include <cuda_fp16.h>

#define EPSF 1e-10f
#define NI 100000
#define NU 100000
#define NR 6
#define BB 512
#define PP 100
#define QQ 40
#define P2 40
#define XS 12  // XT row stride (floats)

typedef unsigned long long ull;

// ---------------- persistent scratch (static device memory) -----------------
__device__ float g_iP[NI * 64];             // item_table @ W1_top (fp32, for combo)
__device__ __half g_iPh[NI * 64];           // fp16 shadow for k2s1 phase B
__device__ float g_uPA1[NU * 64];           // user_table @ A1_bot
__device__ float g_rP[NR * 64];             // rate_table @ W1_bot + gv_b1
__device__ float g_Wf[64 * 64];             // W2 @ A1_top
__device__ float g_bf[64];                  // b2 @ A1_top + b1a
__device__ float g_Wg[64 * 64];             // W2 @ agg_W
__device__ float g_bg[64];                  // b2 @ agg_W
__device__ __half g_T2h[(long)NR * NI * 64]; // T2 (fp16) per (rate,item)
__device__ float g_hoI[BB * QQ * 64];
__device__ float g_hiI[BB * 64];
__device__ float g_hiS[BB * 64];

// ------------------------- f32x2 packed helpers ----------------------------
__device__ __forceinline__ ull pk2(float lo, float hi) {
  ull r; asm("mov.b64 %0, {%1,%2};" : "=l"(r) : "f"(lo), "f"(hi)); return r;
}
__device__ __forceinline__ void fma2(ull& d, ull a, ull b) {
  asm("fma.rn.f32x2 %0, %1, %2, %0;" : "+l"(d) : "l"(a), "l"(b));
}
__device__ __forceinline__ void upk(ull v, float& lo, float& hi) {
  asm("mov.b64 {%0,%1}, %2;" : "=f"(lo), "=f"(hi) : "l"(v));
}

// ---------------------------------------------------------------------------
// packed 5-row warp GEMM (XT stride 8)
// ---------------------------------------------------------------------------
template <int K>
__device__ __forceinline__ void wgemm2(const float* __restrict__ sXT,
                                       const float* __restrict__ sW, int lane,
                                       ull a0[2], ull a1[2], float& s40, float& s41) {
#pragma unroll 8
  for (int k = 0; k < K; k++) {
    ulonglong2 xu = *reinterpret_cast<const ulonglong2*>(sXT + k * 8); // rows 0..3
    float x5 = sXT[k * 8 + 4];
    float2 wv = *reinterpret_cast<const float2*>(sW + k * 64 + 2 * lane);
    ull w0 = pk2(wv.x, wv.x), w1 = pk2(wv.y, wv.y);
    fma2(a0[0], xu.x, w0); fma2(a1[0], xu.x, w1);
    fma2(a0[1], xu.y, w0); fma2(a1[1], xu.y, w1);
    s40 = fmaf(x5, wv.x, s40); s41 = fmaf(x5, wv.y, s41);
  }
}
__device__ __forceinline__ void unpack5(const ull a0[2], const ull a1[2],
                                        float s40, float s41, float acc[5][2]) {
  upk(a0[0], acc[0][0], acc[1][0]); upk(a0[1], acc[2][0], acc[3][0]);
  upk(a1[0], acc[0][1], acc[1][1]); upk(a1[1], acc[2][1], acc[3][1]);
  acc[4][0] = s40; acc[4][1] = s41;
}
__device__ __forceinline__ void wtrans(float* sT, int lane, const float acc[5][2]) {
#pragma unroll
  for (int j = 0; j < 5; j++) {
    sT[(2 * lane) * 8 + j]     = acc[j][0];
    sT[(2 * lane + 1) * 8 + j] = acc[j][1];
  }
}

// ---------------------------------------------------------------------------
// K0_pre (parallel): grid 33.
// ---------------------------------------------------------------------------
__global__ __launch_bounds__(256) void k0_pre(
    const float* __restrict__ rate_table, const float* __restrict__ gv_W1,
    const float* __restrict__ gv_b1, const float* __restrict__ gv_W2,
    const float* __restrict__ gv_b2, const float* __restrict__ atti_W1,
    const float* __restrict__ atti_b1, const float* __restrict__ agg_W) {
  int b = blockIdx.x, t = threadIdx.x;
  if (b < 16) {
    int idx = b * 256 + t;
    int k = idx >> 6, c = idx & 63;
    float s = 0.f;
#pragma unroll 8
    for (int j = 0; j < 64; j++) s = fmaf(gv_W2[k * 64 + j], atti_W1[j * 64 + c], s);
    g_Wf[idx] = s;
  } else if (b < 32) {
    int idx = (b - 16) * 256 + t;
    int k = idx >> 6, c = idx & 63;
    float s = 0.f;
#pragma unroll 8
    for (int j = 0; j < 64; j++) s = fmaf(gv_W2[k * 64 + j], agg_W[j * 64 + c], s);
    g_Wg[idx] = s;
  } else {
    for (int i = t; i < NR * 64; i += 256) {
      int r = i >> 6, c = i & 63;
      float s = gv_b1[c];
      const float* W1b = gv_W1 + 4096;
#pragma unroll 8
      for (int k = 0; k < 64; k++) s = fmaf(rate_table[r * 64 + k], W1b[k * 64 + c], s);
      g_rP[i] = s;
    }
    if (t < 64) {
      float s = atti_b1[t], sg = 0.f;
#pragma unroll 8
      for (int j = 0; j < 64; j++) {
        s = fmaf(gv_b2[j], atti_W1[j * 64 + t], s);
        sg = fmaf(gv_b2[j], agg_W[j * 64 + t], sg);
      }
      g_bf[t] = s;
      g_bg[t] = sg;
    }
  }
}

// ---------------------------------------------------------------------------
// K0_proj (FFMA2; persistent grid-stride over 2500 tiles of 80 rows)
// grid 444 (3 CTAs/SM resident).
// ---------------------------------------------------------------------------
#define SMEM_K0P ((4096 + 4096 + 8 * 64 * XS) * 4)
__global__ __launch_bounds__(256) void k0_proj(
    const float* __restrict__ item_table, const float* __restrict__ user_table,
    const float* __restrict__ gv_W1, const float* __restrict__ atti_W1) {
  extern __shared__ float sm[];
  float* sWa = sm;
  float* sWb = sm + 4096;
  float* sXT = sm + 8192;

  int tid = threadIdx.x, lane = tid & 31, w = tid >> 5;
  for (int i = tid; i < 4096; i += 256) { sWa[i] = gv_W1[i]; sWb[i] = atti_W1[4096 + i]; }
  __syncthreads();
  float* myXT = sXT + w * (64 * XS);

  for (int tile = blockIdx.x; tile < 2500; tile += 444) {
    int rid0 = tile * 80 + w * 10;
    bool half2b = (rid0 >= NI);
    const float* src = half2b ? user_table : item_table;
    const float* sW = half2b ? sWb : sWa;
    float* dst = half2b ? g_uPA1 : g_iP;
    int base = half2b ? (rid0 - NI) : rid0;
#pragma unroll
    for (int j = 0; j < 10; j++) {
      const float* sp = src + (long)(base + j) * 64;
      myXT[lane * XS + j] = sp[lane];
      myXT[(lane + 32) * XS + j] = sp[lane + 32];
    }
    __syncwarp();
    ull a0[5], a1[5];
#pragma unroll
    for (int p = 0; p < 5; p++) { a0[p] = 0ull; a1[p] = 0ull; }
#pragma unroll 8
    for (int k = 0; k < 64; k++) {
      ulonglong2 xu0 = *reinterpret_cast<const ulonglong2*>(myXT + k * XS);
      ulonglong2 xu1 = *reinterpret_cast<const ulonglong2*>(myXT + k * XS + 4);
      ull xp4 = *reinterpret_cast<const ull*>(myXT + k * XS + 8);
      float2 wv = *reinterpret_cast<const float2*>(sW + k * 64 + 2 * lane);
      ull w0 = pk2(wv.x, wv.x), w1 = pk2(wv.y, wv.y);
      fma2(a0[0], xu0.x, w0); fma2(a1[0], xu0.x, w1);
      fma2(a0[1], xu0.y, w0); fma2(a1[1], xu0.y, w1);
      fma2(a0[2], xu1.x, w0); fma2(a1[2], xu1.x, w1);
      fma2(a0[3], xu1.y, w0); fma2(a1[3], xu1.y, w1);
      fma2(a0[4], xp4, w0);   fma2(a1[4], xp4, w1);
    }
#pragma unroll
    for (int p = 0; p < 5; p++) {
      float r0c0, r1c0, r0c1, r1c1;
      upk(a0[p], r0c0, r1c0); upk(a1[p], r0c1, r1c1);
      long o0 = (long)(base + 2 * p) * 64 + 2 * lane;
      long o1 = (long)(base + 2 * p + 1) * 64 + 2 * lane;
      *reinterpret_cast<float2*>(dst + o0) = make_float2(r0c0, r0c1);
      *reinterpret_cast<float2*>(dst + o1) = make_float2(r1c0, r1c1);
      if (!half2b) {
        *reinterpret_cast<__half2*>(g_iPh + o0) = __floats2half2_rn(r0c0, r0c1);
        *reinterpret_cast<__half2*>(g_iPh + o1) = __floats2half2_rn(r1c0, r1c1);
      }
    }
    __syncwarp();
  }
}

// ---------------------------------------------------------------------------
// K0_combo (FFMA2, fp16 T2 output; persistent grid-stride over 7500 tiles)
// grid 592 (4 CTAs/SM resident).
// ---------------------------------------------------------------------------
#define SMEM_K0C ((4096 + 8 * 64 * XS + 384 + 64) * 4)
__global__ __launch_bounds__(256) void k0_combo() {
  extern __shared__ float sm[];
  float* sWf = sm;                  // 4096
  float* sXT = sm + 4096;           // 6144
  float* srP = sm + 4096 + 6144;    // 384
  float* sbf = srP + 384;           // 64

  int tid = threadIdx.x, lane = tid & 31, w = tid >> 5;
  for (int i = tid; i < 4096; i += 256) sWf[i] = g_Wf[i];
  for (int i = tid; i < 384; i += 256) srP[i] = g_rP[i];
  if (tid < 64) sbf[tid] = g_bf[tid];
  __syncthreads();
  float* myXT = sXT + w * (64 * XS);

  float2 bb2 = *reinterpret_cast<const float2*>(sbf + 2 * lane);
  ull b20 = pk2(bb2.x, bb2.x), b21 = pk2(bb2.y, bb2.y);

  for (int tile = blockIdx.x; tile < 7500; tile += 592) {
    int rid0 = tile * 80 + w * 10;
    int r = rid0 / NI;
    int i0 = rid0 - r * NI;
    const float* rp = srP + r * 64;
    float rp0 = rp[lane], rp1 = rp[lane + 32];
#pragma unroll
    for (int j = 0; j < 10; j++) {
      const float* ip = g_iP + (long)(i0 + j) * 64;
      myXT[lane * XS + j] = fmaxf(ip[lane] + rp0, 0.f);
      myXT[(lane + 32) * XS + j] = fmaxf(ip[lane + 32] + rp1, 0.f);
    }
    __syncwarp();
    ull a20[5], a21[5];
#pragma unroll
    for (int p = 0; p < 5; p++) { a20[p] = b20; a21[p] = b21; }
#pragma unroll 8
    for (int k = 0; k < 64; k++) {
      ulonglong2 xu0 = *reinterpret_cast<const ulonglong2*>(myXT + k * XS);
      ulonglong2 xu1 = *reinterpret_cast<const ulonglong2*>(myXT + k * XS + 4);
      ull xp4 = *reinterpret_cast<const ull*>(myXT + k * XS + 8);
      float2 w2v = *reinterpret_cast<const float2*>(sWf + k * 64 + 2 * lane);
      ull w20 = pk2(w2v.x, w2v.x), w21 = pk2(w2v.y, w2v.y);
      fma2(a20[0], xu0.x, w20); fma2(a21[0], xu0.x, w21);
      fma2(a20[1], xu0.y, w20); fma2(a21[1], xu0.y, w21);
      fma2(a20[2], xu1.x, w20); fma2(a21[2], xu1.x, w21);
      fma2(a20[3], xu1.y, w20); fma2(a21[3], xu1.y, w21);
      fma2(a20[4], xp4, w20);   fma2(a21[4], xp4, w21);
    }
#pragma unroll
    for (int p = 0; p < 5; p++) {
      float r0c0, r1c0, r0c1, r1c1;
      upk(a20[p], r0c0, r1c0); upk(a21[p], r0c1, r1c1);
      long o0 = (long)(rid0 + 2 * p) * 64 + 2 * lane;
      long o1 = (long)(rid0 + 2 * p + 1) * 64 + 2 * lane;
      *reinterpret_cast<__half2*>(g_T2h + o0) = __floats2half2_rn(r0c0, r0c1);
      *reinterpret_cast<__half2*>(g_T2h + o1) = __floats2half2_rn(r1c0, r1c1);
    }
    __syncwarp();
  }
}

// ---------------------------------------------------------------------------
// K2s1: merged attention kernel, fused oct-slice, fp16 T2 + fp16 iP gathers.
// Persistent grid-stride over 2624 virtual blocks; grid 740 (5 CTAs/SM).
// vb [0,64): item branch; vb [64, 2624): social branch.
// ---------------------------------------------------------------------------
__global__ __launch_bounds__(256, 5) void k2s1_attn(
    const int* __restrict__ uids,
    const int* __restrict__ u_user, const int* __restrict__ u_user_item,
    const int* __restrict__ u_item,
    const float* __restrict__ agg_b,
    const float* __restrict__ atti_W2, const float* __restrict__ atti_b2) {
  __shared__ float sWg[4096];
  __shared__ float srP[384];
  __shared__ float sbAgg[64];
  __shared__ float sbg[64];
  __shared__ float sA2[64];
  __shared__ float sPC[8][64];
  __shared__ float sPart[8][4][64];
  __shared__ float sZ[8][64];

  int tid = threadIdx.x, lane = tid & 31, w = tid >> 5;
  for (int i = tid; i < 4096; i += 256) sWg[i] = g_Wg[i];
  for (int i = tid; i < 384; i += 256) srP[i] = g_rP[i];
  if (tid < 64) { sbAgg[tid] = agg_b[tid]; sbg[tid] = g_bg[tid]; sA2[tid] = atti_W2[tid]; }
  __syncthreads();
  float cb = atti_b2[0];
  int li = lane & 7, oct = lane >> 3;
  float4 a2r0 = *reinterpret_cast<const float4*>(sA2 + li * 8);
  float4 a2r1 = *reinterpret_cast<const float4*>(sA2 + li * 8 + 4);

  for (int vb = blockIdx.x; vb < 2624; vb += 740) {
    bool isItem = (vb < 64);
    int unit = isItem ? (vb * 8 + w) : ((vb - 64) * 8 + w);
    int P = isItem ? PP : P2;
    int u = isItem ? uids[unit] : u_user[unit];
    const int2* ips = reinterpret_cast<const int2*>(
        isItem ? (u_item + (long)unit * (PP * 2)) : (u_user_item + (long)unit * (P2 * 2)));
    float* outp = isItem ? (g_hiI + (long)unit * 64) : (g_hoI + (long)unit * 64);

    sPC[w][lane] = g_uPA1[(long)u * 64 + lane];
    sPC[w][lane + 32] = g_uPA1[(long)u * 64 + 32 + lane];
    __syncwarp();

    float4 acca = make_float4(0.f, 0.f, 0.f, 0.f);
    float4 accb = make_float4(0.f, 0.f, 0.f, 0.f);
    float den = 0.f;
    int niter = P >> 2;
    for (int it = 0; it < niter; it++) {
      int r = it * 4 + oct;
      int2 idx = ips[r];
      float m = (idx.x > 0) ? 1.f : 0.f;
      long rid = (long)(idx.y * NI + idx.x);
      uint4 traw = *reinterpret_cast<const uint4*>(g_T2h + rid * 64 + li * 8);
      __half2* th = reinterpret_cast<__half2*>(&traw);
      float2 t20 = __half22float2(th[0]);
      float2 t21 = __half22float2(th[1]);
      float2 t22 = __half22float2(th[2]);
      float2 t23 = __half22float2(th[3]);
      uint4 iraw = *reinterpret_cast<const uint4*>(g_iPh + (long)idx.x * 64 + li * 8);
      __half2* ih = reinterpret_cast<__half2*>(&iraw);
      float2 ip0 = __half22float2(ih[0]);
      float2 ip1 = __half22float2(ih[1]);
      float2 ip2 = __half22float2(ih[2]);
      float2 ip3 = __half22float2(ih[3]);
      const float4* rpp = reinterpret_cast<const float4*>(srP + idx.y * 64 + li * 8);
      float4 rpa = rpp[0], rpb = rpp[1];
      const float4* pcp = reinterpret_cast<const float4*>(&sPC[w][li * 8]);
      float4 pcr0 = pcp[0], pcr1 = pcp[1];
      float s;
      s = fmaxf(fmaf(m, pcr0.x, t20.x), 0.f) * a2r0.x;
      s = fmaf(fmaxf(fmaf(m, pcr0.y, t20.y), 0.f), a2r0.y, s);
      s = fmaf(fmaxf(fmaf(m, pcr0.z, t21.x), 0.f), a2r0.z, s);
      s = fmaf(fmaxf(fmaf(m, pcr0.w, t21.y), 0.f), a2r0.w, s);
      s = fmaf(fmaxf(fmaf(m, pcr1.x, t22.x), 0.f), a2r1.x, s);
      s = fmaf(fmaxf(fmaf(m, pcr1.y, t22.y), 0.f), a2r1.y, s);
      s = fmaf(fmaxf(fmaf(m, pcr1.z, t23.x), 0.f), a2r1.z, s);
      s = fmaf(fmaxf(fmaf(m, pcr1.w, t23.y), 0.f), a2r1.w, s);
      s += __shfl_xor_sync(0xffffffffu, s, 1);
      s += __shfl_xor_sync(0xffffffffu, s, 2);
      s += __shfl_xor_sync(0xffffffffu, s, 4);
      float al = __expf(s + cb) * m;
      den += al;
      acca.x = fmaf(al, fmaxf(ip0.x + rpa.x, 0.f), acca.x);
      acca.y = fmaf(al, fmaxf(ip0.y + rpa.y, 0.f), acca.y);
      acca.z = fmaf(al, fmaxf(ip1.x + rpa.z, 0.f), acca.z);
      acca.w = fmaf(al, fmaxf(ip1.y + rpa.w, 0.f), acca.w);
      accb.x = fmaf(al, fmaxf(ip2.x + rpb.x, 0.f), accb.x);
      accb.y = fmaf(al, fmaxf(ip2.y + rpb.y, 0.f), accb.y);
      accb.z = fmaf(al, fmaxf(ip3.x + rpb.z, 0.f), accb.z);
      accb.w = fmaf(al, fmaxf(ip3.y + rpb.w, 0.f), accb.w);
    }
#pragma unroll
    for (int o = 16; o; o >>= 1) den += __shfl_xor_sync(0xffffffffu, den, o);
    den *= 0.125f;
    float dinv = 1.f / (den + EPSF);
    float sig = den * dinv;

    *reinterpret_cast<float4*>(&sPart[w][oct][li * 8]) = acca;
    *reinterpret_cast<float4*>(&sPart[w][oct][li * 8 + 4]) = accb;
    __syncwarp();
    int c0 = 2 * lane;
    float zx = sPart[w][0][c0] + sPart[w][1][c0] + sPart[w][2][c0] + sPart[w][3][c0];
    float zy = sPart[w][0][c0 + 1] + sPart[w][1][c0 + 1] + sPart[w][2][c0 + 1] + sPart[w][3][c0 + 1];
    sZ[w][c0] = zx * dinv;
    sZ[w][c0 + 1] = zy * dinv;
    __syncwarp();

    float ox = fmaf(sig, sbg[c0], sbAgg[c0]);
    float oy = fmaf(sig, sbg[c0 + 1], sbAgg[c0 + 1]);
#pragma unroll 8
    for (int k = 0; k < 64; k++) {
      float zk = sZ[w][k];
      float2 wk = *reinterpret_cast<const float2*>(sWg + k * 64 + c0);
      ox = fmaf(zk, wk.x, ox);
      oy = fmaf(zk, wk.y, oy);
    }
    *reinterpret_cast<float2*>(outp + c0) =
        make_float2(fmaxf(ox, 0.f), fmaxf(oy, 0.f));
    __syncwarp();
  }
}

// ---------------------------------------------------------------------------
// K2b: beta attention over q + h_iS. FFMA2 GEMM, 2 batch elements per CTA.
// ---------------------------------------------------------------------------
#define SMEM_K2B (20784 * 4)
__global__ __launch_bounds__(256) void k2b_user(
    const int* __restrict__ u_user, const float* __restrict__ user_table,
    const float* __restrict__ attu_W1, const float* __restrict__ attu_b1,
    const float* __restrict__ attu_W2, const float* __restrict__ attu_b2,
    const float* __restrict__ aggn_W, const float* __restrict__ aggn_b) {
  extern __shared__ float sm[];
  float* sU1 = sm;
  float* sAggn = sm + 8192;
  float* sw2u = sm + 12288;
  float* sb1u = sm + 12352;
  float* sbAggn = sm + 12416;
  float* sZ = sm + 12480;
  float* sBeta = sm + 12544;
  float* sRed = sm + 12584;
  float* sXT = sm + 12592;

  int tid = threadIdx.x, lane = tid & 31, w = tid >> 5;
  for (int i = tid; i < 8192; i += 256) sU1[i] = attu_W1[i];
  for (int i = tid; i < 4096; i += 256) sAggn[i] = aggn_W[i];
  if (tid < 64) { sw2u[tid] = attu_W2[tid]; sb1u[tid] = attu_b1[tid]; sbAggn[tid] = aggn_b[tid]; }
  __syncthreads();
  float cb2u = attu_b2[0];
  float* myXT = sXT + w * 1024;
  int rowbase = w * 5;

  for (int bi = 0; bi < 2; bi++) {
    int b = blockIdx.x * 2 + bi;
    __syncthreads();
    float msk[5];
#pragma unroll
    for (int j = 0; j < 5; j++) {
      int row = rowbase + j;
      int uq = u_user[b * 40 + row];
      msk[j] = (uq > 0) ? 1.f : 0.f;
      const float* hp = g_hoI + (long)(b * 40 + row) * 64;
      const float* up = user_table + (long)uq * 64;
      myXT[lane * 8 + j] = hp[lane];
      myXT[(lane + 32) * 8 + j] = hp[lane + 32];
      myXT[(lane + 64) * 8 + j] = up[lane];
      myXT[(lane + 96) * 8 + j] = up[lane + 32];
    }
    __syncwarp();
    float bc0 = sb1u[2 * lane], bc1 = sb1u[2 * lane + 1];
    ull a0[2], a1[2];
    float s40 = bc0, s41 = bc1;
    a0[0] = pk2(bc0, bc0); a0[1] = a0[0];
    a1[0] = pk2(bc1, bc1); a1[1] = a1[0];
    wgemm2<128>(myXT, sU1, lane, a0, a1, s40, s41);
    float acc[5][2];
    unpack5(a0, a1, s40, s41, acc);
    float w0 = sw2u[2 * lane], w1 = sw2u[2 * lane + 1];
#pragma unroll
    for (int j = 0; j < 5; j++) {
      float p = fmaf(fmaxf(acc[j][0], 0.f), w0, fmaxf(acc[j][1], 0.f) * w1);
#pragma unroll
      for (int o = 16; o; o >>= 1) p += __shfl_xor_sync(0xffffffffu, p, o);
      if (lane == 0) sBeta[rowbase + j] = expf(p + cb2u) * msk[j];
    }
    __syncthreads();
    if (tid < 32) {
      float s = 0.f;
      for (int r = lane; r < 40; r += 32) s += sBeta[r];
#pragma unroll
      for (int o = 16; o; o >>= 1) s += __shfl_xor_sync(0xffffffffu, s, o);
      if (lane == 0) sRed[0] = s;
    }
    __syncthreads();
    float dinv = 1.f / (sRed[0] + EPSF);
    if (tid < 64) {
      float s = 0.f;
      for (int r = 0; r < 40; r++) s = fmaf(sBeta[r], g_hoI[(long)(b * 40 + r) * 64 + tid], s);
      sZ[tid] = s * dinv;
    }
    __syncthreads();
    if (tid < 64) {
      float s = sbAggn[tid];
      for (int k = 0; k < 64; k++) s = fmaf(sZ[k], sAggn[k * 64 + tid], s);
      g_hiS[b * 64 + tid] = fmaxf(s, 0.f);
    }
  }
}

// ---------------------------------------------------------------------------
// K3: final 3-layer combine MLP (FFMA2).
// ---------------------------------------------------------------------------
#define SMEM_K3 (24768 * 4)
__global__ __launch_bounds__(256) void k3_final(
    const float* __restrict__ cm_W1, const float* __restrict__ cm_b1,
    const float* __restrict__ cm_W2, const float* __restrict__ cm_b2,
    const float* __restrict__ cm_W3, const float* __restrict__ cm_b3,
    float* __restrict__ out) {
  extern __shared__ float sm[];
  float* sC1 = sm;
  float* sC2 = sm + 8192;
  float* sC3 = sm + 12288;
  float* sb1 = sm + 16384;
  float* sb2 = sm + 16448;
  float* sb3 = sm + 16512;
  float* sXT = sm + 16576;

  int tid = threadIdx.x, lane = tid & 31, w = tid >> 5;
  for (int i = tid; i < 8192; i += 256) sC1[i] = cm_W1[i];
  for (int i = tid; i < 4096; i += 256) { sC2[i] = cm_W2[i]; sC3[i] = cm_W3[i]; }
  if (tid < 64) { sb1[tid] = cm_b1[tid]; sb2[tid] = cm_b2[tid]; sb3[tid] = cm_b3[tid]; }
  __syncthreads();
  float* myXT = sXT + w * 1024;
  int rowbase = blockIdx.x * 40 + w * 5;
#pragma unroll
  for (int j = 0; j < 5; j++) {
    int row = rowbase + j;
    float x0 = 0.f, x1 = 0.f, x2 = 0.f, x3 = 0.f;
    if (row < BB) {
      x0 = g_hiI[row * 64 + lane];
      x1 = g_hiI[row * 64 + 32 + lane];
      x2 = g_hiS[row * 64 + lane];
      x3 = g_hiS[row * 64 + 32 + lane];
    }
    myXT[lane * 8 + j] = x0;
    myXT[(lane + 32) * 8 + j] = x1;
    myXT[(lane + 64) * 8 + j] = x2;
    myXT[(lane + 96) * 8 + j] = x3;
  }
  __syncwarp();
  float acc[5][2];
  {
    float bc0 = sb1[2 * lane], bc1 = sb1[2 * lane + 1];
    ull a0[2], a1[2];
    float s40 = bc0, s41 = bc1;
    a0[0] = pk2(bc0, bc0); a0[1] = a0[0];
    a1[0] = pk2(bc1, bc1); a1[1] = a1[0];
    wgemm2<128>(myXT, sC1, lane, a0, a1, s40, s41);
    unpack5(a0, a1, s40, s41, acc);
  }
#pragma unroll
  for (int j = 0; j < 5; j++) { acc[j][0] = fmaxf(acc[j][0], 0.f); acc[j][1] = fmaxf(acc[j][1], 0.f); }
  __syncwarp();
  wtrans(myXT, lane, acc);
  __syncwarp();
  {
    float bc0 = sb2[2 * lane], bc1 = sb2[2 * lane + 1];
    ull a0[2], a1[2];
    float s40 = bc0, s41 = bc1;
    a0[0] = pk2(bc0, bc0); a0[1] = a0[0];
    a1[0] = pk2(bc1, bc1); a1[1] = a1[0];
    wgemm2<64>(myXT, sC2, lane, a0, a1, s40, s41);
    unpack5(a0, a1, s40, s41, acc);
  }
#pragma unroll
  for (int j = 0; j < 5; j++) { acc[j][0] = fmaxf(acc[j][0], 0.f); acc[j][1] = fmaxf(acc[j][1], 0.f); }
  __syncwarp();
  wtrans(myXT, lane, acc);
  __syncwarp();
  {
    float bc0 = sb3[2 * lane], bc1 = sb3[2 * lane + 1];
    ull a0[2], a1[2];
    float s40 = bc0, s41 = bc1;
    a0[0] = pk2(bc0, bc0); a0[1] = a0[0];
    a1[0] = pk2(bc1, bc1); a1[1] = a1[0];
    wgemm2<64>(myXT, sC3, lane, a0, a1, s40, s41);
    unpack5(a0, a1, s40, s41, acc);
  }
#pragma unroll
  for (int j = 0; j < 5; j++) {
    int row = rowbase + j;
    if (row < BB) {
      out[row * 64 + 2 * lane]     = fmaxf(acc[j][0], 0.f);
      out[row * 64 + 2 * lane + 1] = fmaxf(acc[j][1], 0.f);
    }
  }
}

// ---------------------------------------------------------------------------
extern "C" void kernel_launch(void* const* d_in, const int* in_sizes, int n_in,
                              void* d_out, int out_size) {
  const int* uids        = (const int*)d_in[0];
  const int* u_item      = (const int*)d_in[1];
  const int* u_user      = (const int*)d_in[2];
  const int* u_user_item = (const int*)d_in[3];
  const float* user_table = (const float*)d_in[4];
  const float* item_table = (const float*)d_in[5];
  const float* rate_table = (const float*)d_in[6];
  const float* gv_W1 = (const float*)d_in[7];
  const float* gv_b1 = (const float*)d_in[8];
  const float* gv_W2 = (const float*)d_in[9];
  const float* gv_b2 = (const float*)d_in[10];
  const float* atti_W1 = (const float*)d_in[11];
  const float* atti_b1 = (const float*)d_in[12];
  const float* atti_W2 = (const float*)d_in[13];
  const float* atti_b2 = (const float*)d_in[14];
  const float* agg_W = (const float*)d_in[15];
  const float* agg_b = (const float*)d_in[16];
  const float* attu_W1 = (const float*)d_in[17];
  const float* attu_b1 = (const float*)d_in[18];
  const float* attu_W2 = (const float*)d_in[19];
  const float* attu_b2 = (const float*)d_in[20];
  const float* aggn_W = (const float*)d_in[21];
  const float* aggn_b = (const float*)d_in[22];
  const float* cm_W1 = (const float*)d_in[23];
  const float* cm_b1 = (const float*)d_in[24];
  const float* cm_W2 = (const float*)d_in[25];
  const float* cm_b2 = (const float*)d_in[26];
  const float* cm_W3 = (const float*)d_in[27];
  const float* cm_b3 = (const float*)d_in[28];
  float* out = (float*)d_out;

  cudaFuncSetAttribute(k0_proj,  cudaFuncAttributeMaxDynamicSharedMemorySize, SMEM_K0P);
  cudaFuncSetAttribute(k0_combo, cudaFuncAttributeMaxDynamicSharedMemorySize, SMEM_K0C);
  cudaFuncSetAttribute(k2b_user, cudaFuncAttributeMaxDynamicSharedMemorySize, SMEM_K2B);
  cudaFuncSetAttribute(k3_final, cudaFuncAttributeMaxDynamicSharedMemorySize, SMEM_K3);

  k0_pre<<<33, 256>>>(rate_table, gv_W1, gv_b1, gv_W2, gv_b2, atti_W1, atti_b1, agg_W);
  k0_proj<<<444, 256, SMEM_K0P>>>(item_table, user_table, gv_W1, atti_W1);
  k0_combo<<<592, 256, SMEM_K0C>>>();
  k2s1_attn<<<740, 256>>>(uids, u_user, u_user_item, u_item,
                          agg_b, atti_W2, atti_b2);
  k2b_user<<<256, 256, SMEM_K2B>>>(u_user, user_table, attu_W1, attu_b1, attu_W2,
                                   attu_b2, aggn_W, aggn_b);
  k3_final<<<13, 256, SMEM_K3>>>(cm_W1, cm_b1, cm_W2, cm_b2, cm_W3, cm_b3, out);
}